// round 12
// baseline (speedup 1.0000x reference)
#include <cuda_runtime.h>
#include <cuda_fp16.h>
#include <cstdint>
#include <cstddef>

// Problem constants
#define BSZ 4096
#define TSZ 100
#define FSZ 13
#define HSZ 100
#define G4  400

// GEMM constants
#define KP   112
#define LDA  120
#define LDB  120

// Recurrent kernel constants
#define RW    13
#define RTH   (RW*32)
#define W2N   23296         // W fragment words (52 ntiles * 7 kt * 64)
#define HROW  68            // h row stride in words
#define MROW  16            // batch rows per CTA (2 CTAs per SM)
#define HBUFW (MROW*HROW)   // 1088 words per buffer

// ---------------------------------------------------------------------------
// Scratch (device globals)
// ---------------------------------------------------------------------------
__device__ __half g_h0hi[(size_t)BSZ * TSZ * HSZ];
__device__ __half g_h0lo[(size_t)BSZ * TSZ * HSZ];
__device__ __half g_bh[G4 * KP];                  // W_ih1 fp16 (gemm layout)
__device__ float g_zpack [(size_t)BSZ * TSZ * G4];
__device__ float g_z0pack[(size_t)BSZ * TSZ * G4];
__device__ int   g_off_arr[BSZ + 1];
__device__ uint32_t g_w2h0[W2N];                  // Whh0 fp16 frag layout
__device__ uint32_t g_w2h1[W2N];                  // Whh1 fp16 frag layout

// ---------------------------------------------------------------------------
// Helpers
// ---------------------------------------------------------------------------
__device__ __forceinline__ float tanha(float x) {
    float y;
    asm("tanh.approx.f32 %0, %1;" : "=f"(y) : "f"(x));
    return y;
}
__device__ __forceinline__ float siga(float x) {
    return fmaf(0.5f, tanha(0.5f * x), 0.5f);
}
__device__ __forceinline__ void ffma2(unsigned long long &d,
                                      unsigned long long a,
                                      unsigned long long b) {
    asm("fma.rn.f32x2 %0, %1, %2, %0;" : "+l"(d) : "l"(a), "l"(b));
}
__device__ __forceinline__ unsigned long long pk(float lo, float hi) {
    unsigned long long r;
    asm("mov.b64 %0, {%1, %2};" : "=l"(r) : "f"(lo), "f"(hi));
    return r;
}
__device__ __forceinline__ float psum(unsigned long long a) {
    float lo = __uint_as_float((unsigned)(a & 0xffffffffull));
    float hi = __uint_as_float((unsigned)(a >> 32));
    return lo + hi;
}
__device__ __forceinline__ void mma_fp16(float* d, const uint32_t* a,
                                         uint32_t b0, uint32_t b1) {
    asm volatile(
        "mma.sync.aligned.m16n8k16.row.col.f32.f16.f16.f32 "
        "{%0,%1,%2,%3}, {%4,%5,%6,%7}, {%8,%9}, {%0,%1,%2,%3};"
        : "+f"(d[0]), "+f"(d[1]), "+f"(d[2]), "+f"(d[3])
        : "r"(a[0]), "r"(a[1]), "r"(a[2]), "r"(a[3]), "r"(b0), "r"(b1));
}
__device__ __forceinline__ void ldsm4(uint32_t* r, uint32_t addr) {
    asm volatile("ldmatrix.sync.aligned.m8n8.x4.shared.b16 {%0,%1,%2,%3}, [%4];"
        : "=r"(r[0]), "=r"(r[1]), "=r"(r[2]), "=r"(r[3]) : "r"(addr));
}
__device__ __forceinline__ uint32_t smem_u32(const void* p) {
    uint32_t a;
    asm("{ .reg .u64 t; cvta.to.shared.u64 t, %1; cvt.u32.u64 %0, t; }"
        : "=r"(a) : "l"(p));
    return a;
}
__device__ __forceinline__ void split_h2(float f0, float f1,
                                         uint32_t &hw, uint32_t &lw) {
    __half2 h2 = __float22half2_rn(make_float2(f0, f1));
    hw = *(uint32_t*)&h2;
    float2 back = __half22float2(h2);
    __half2 l2 = __float22half2_rn(make_float2(f0 - back.x, f1 - back.y));
    lw = *(uint32_t*)&l2;
}

// ===========================================================================
// Kernel S: exclusive prefix scan of lengths (1 CTA)
// ===========================================================================
__global__ void __launch_bounds__(512, 1) k_scan(const int* __restrict__ lengths)
{
    __shared__ int s[512];
    const int tid = threadIdx.x;
    const int base = tid * 8;
    int v[8]; int loc = 0;
    #pragma unroll
    for (int i = 0; i < 8; i++) { v[i] = lengths[base + i]; loc += v[i]; }
    s[tid] = loc;
    __syncthreads();
    for (int d = 1; d < 512; d <<= 1) {
        int t = (tid >= d) ? s[tid - d] : 0;
        __syncthreads();
        s[tid] += t;
        __syncthreads();
    }
    int run = s[tid] - loc;
    #pragma unroll
    for (int i = 0; i < 8; i++) { g_off_arr[base + i] = run; run += v[i]; }
    if (tid == 511) g_off_arr[BSZ] = s[511];
}

// ===========================================================================
// Kernel W1: W_ih1 -> fp16 (gemm layout, k-padded)
// ===========================================================================
__global__ void __launch_bounds__(256, 1) k_wsplit(const float* __restrict__ Wih1)
{
    int idx = blockIdx.x * 256 + threadIdx.x;
    if (idx < G4 * KP) {
        int n = idx / KP, k = idx % KP;
        float v = (k < HSZ) ? Wih1[n * HSZ + k] : 0.f;
        g_bh[idx] = __float2half(v);
    }
}

// ===========================================================================
// Kernel W2: Whh -> fp16 pair-packed fragment layout
// ===========================================================================
__global__ void __launch_bounds__(256, 1)
k_wprep(const float* __restrict__ W, uint32_t* __restrict__ dh)
{
    int j = blockIdx.x * 256 + threadIdx.x;
    if (j >= W2N) return;
    int sel = j & 1;
    int pp  = (j >> 1) & 31;
    int tg  = pp >> 3, g = pp & 7;
    int grp = j >> 6;
    int kt  = grp % 7, n = grp / 7;
    int row = n * 8 + g;
    int gate = row / 104, u = row % 104;
    int k    = kt * 16 + 2 * tg + 8 * sel;
    float f0 = (u < HSZ && k     < HSZ) ? W[(gate * HSZ + u) * HSZ + k]     : 0.f;
    float f1 = (u < HSZ && k + 1 < HSZ) ? W[(gate * HSZ + u) * HSZ + k + 1] : 0.f;
    __half2 h2 = __float22half2_rn(make_float2(f0, f1));
    dh[j] = *(uint32_t*)&h2;
}

// ===========================================================================
// Kernel Z0: g_z0pack = bias0 + x @ Wih0^T (packed rows, fp32)
// ===========================================================================
__global__ void __launch_bounds__(512, 1)
k_zx0(const float* __restrict__ x, const int* __restrict__ lengths,
      const float* __restrict__ Wih0,
      const float* __restrict__ bih0, const float* __restrict__ bhh0)
{
    __shared__ float sX[1400];
    __shared__ int sLen[32], sOff[32];
    const int tid = threadIdx.x;
    const int grow0 = blockIdx.x * 32;
    if (tid < 32) {
        sLen[tid] = lengths[grow0 + tid];
        sOff[tid] = g_off_arr[grow0 + tid];
    }
    const int u = tid;
    const bool act = (u < G4);
    unsigned long long wp[7];
    float b = 0.f;
    if (act) {
        float wr[14];
        #pragma unroll
        for (int k = 0; k < FSZ; k++) wr[k] = Wih0[u * FSZ + k];
        wr[13] = 0.f;
        #pragma unroll
        for (int i = 0; i < 7; i++) wp[i] = pk(wr[2*i], wr[2*i+1]);
        b = bih0[u] + bhh0[u];
    }
    __syncthreads();

    for (int r = 0; r < 32; r++) {
        const int len = sLen[r], off = sOff[r];
        __syncthreads();
        const float* xs = x + (size_t)(grow0 + r) * (TSZ * FSZ);
        for (int i = tid; i < 1400; i += 512) {
            int t = i / 14, k = i % 14;
            sX[i] = (k < FSZ) ? xs[t * FSZ + k] : 0.f;
        }
        __syncthreads();
        if (act) {
            for (int t = 0; t < len; t++) {
                unsigned long long acc = pk(b, 0.f);
                #pragma unroll
                for (int kp = 0; kp < 7; kp++)
                    ffma2(acc, wp[kp], *(const unsigned long long*)&sX[t*14 + 2*kp]);
                g_z0pack[(size_t)(off + t) * G4 + u] = psum(acc);
            }
        }
    }
}

// ===========================================================================
// Kernel R: fp16x2 tensor LSTM — R8 recipe, M=16 rows/CTA, 2 CTAs per SM
// ===========================================================================
template<int MODE>
__global__ void __launch_bounds__(RTH, 2)
k_rec(const int* __restrict__ lengths,
      const float* __restrict__ Wfc, const float* __restrict__ bfc,
      float* __restrict__ out)
{
    extern __shared__ char smc[];
    uint32_t* sW   = (uint32_t*)(smc);                 // 93184 B
    uint32_t* sHhi = (uint32_t*)(smc + 93184);         // 2 x 4352 B
    uint32_t* sHlo = (uint32_t*)(smc + 101888);        // 2 x 4352 B
    int*   sLen = (int*)(smc + 110592);                // 16
    int*   sOff = (int*)(smc + 110656);                // 16
    float* sWf  = (float*)(smc + 110720);              // 100 floats
    float* sHF  = (float*)(smc + 93184);               // fc reuse (after loop)

    const uint32_t* gw   = MODE ? g_w2h1 : g_w2h0;
    const float*    zsrc = MODE ? g_zpack : g_z0pack;

    const int tid = threadIdx.x;
    const int grow0 = blockIdx.x * MROW;

    for (int i = tid; i < W2N; i += RTH) sW[i] = gw[i];
    for (int i = tid; i < 2 * HBUFW; i += RTH) { sHhi[i] = 0u; sHlo[i] = 0u; }
    if (tid < MROW) {
        sLen[tid] = lengths[grow0 + tid];
        sOff[tid] = g_off_arr[grow0 + tid];
    }
    if (MODE == 1 && tid < HSZ) sWf[tid] = Wfc[tid];
    __syncthreads();

    int Lmax = 0;
    #pragma unroll
    for (int r = 0; r < MROW; r++) Lmax = max(Lmax, sLen[r]);

    const int w = tid >> 5, lane = tid & 31;
    const int g = lane >> 2, tg = lane & 3;
    const int u0 = w * 8 + 2 * tg;
    const bool cv = (u0 < HSZ);

    const uint32_t sb = smem_u32(smc);
    const uint32_t lmoff = ((lane & 15) * HROW + (lane >> 4) * 4) * 4;
    const uint32_t hHiB = sb + 93184 + lmoff;
    const uint32_t hLoB = sb + 101888 + lmoff;

    int rown[2], lenr[2], offr[2];
    #pragma unroll
    for (int ri = 0; ri < 2; ri++) {
        rown[ri] = ri * 8 + g;
        lenr[ri] = sLen[rown[ri]];
        offr[ri] = sOff[rown[ri]];
    }
    float c[2][2] = {{0.f,0.f},{0.f,0.f}};
    float h[2][2] = {{0.f,0.f},{0.f,0.f}};

    int p = 0;
    #pragma unroll 1
    for (int t = 0; t < Lmax; t++) {
        // z(t) prefetch (LDG issued first, consumed after the MMA block)
        float2 zn[2][4];
        #pragma unroll
        for (int ri = 0; ri < 2; ri++) {
            const bool lv = cv && (t < lenr[ri]);
            const size_t zb = (size_t)(offr[ri] + t) * G4;
            #pragma unroll
            for (int G = 0; G < 4; G++)
                zn[ri][G] = lv ? *(const float2*)&zsrc[zb + G * HSZ + u0]
                               : make_float2(0.f, 0.f);
        }

        float D[4][4];
        #pragma unroll
        for (int G = 0; G < 4; G++)
            #pragma unroll
            for (int q = 0; q < 4; q++) D[G][q] = 0.f;

        const uint32_t hHi = hHiB + p * 4352;
        const uint32_t hLo = hLoB + p * 4352;
        #pragma unroll
        for (int kt = 0; kt < 7; kt++) {
            uint32_t ahi[4], alo[4];
            ldsm4(ahi, hHi + kt * 32);
            ldsm4(alo, hLo + kt * 32);
            #pragma unroll
            for (int G = 0; G < 4; G++) {
                const int b2 = (((G * 13 + w) * 7 + kt) * 32 + tg * 8 + g) * 2;
                uint2 bh = *(const uint2*)&sW[b2];
                mma_fp16(D[G], ahi, bh.x, bh.y);
                mma_fp16(D[G], alo, bh.x, bh.y);
            }
        }

        // activation + state update + stage h(t+1) into buffer 1-p
        uint32_t* Nh = sHhi + (1 - p) * HBUFW;
        uint32_t* Nl = sHlo + (1 - p) * HBUFW;
        #pragma unroll
        for (int ri = 0; ri < 2; ri++) {
            const bool upd = cv && (t < lenr[ri]);
            #pragma unroll
            for (int j = 0; j < 2; j++) {
                float zi = D[0][ri * 2 + j] + (j ? zn[ri][0].y : zn[ri][0].x);
                float zf = D[1][ri * 2 + j] + (j ? zn[ri][1].y : zn[ri][1].x);
                float zg = D[2][ri * 2 + j] + (j ? zn[ri][2].y : zn[ri][2].x);
                float zo = D[3][ri * 2 + j] + (j ? zn[ri][3].y : zn[ri][3].x);
                float cn = siga(zf) * c[ri][j] + siga(zi) * tanha(zg);
                float hn = siga(zo) * tanha(cn);
                if (upd) { c[ri][j] = cn; h[ri][j] = hn; }
            }
            uint32_t hw, lw;
            split_h2(h[ri][0], h[ri][1], hw, lw);
            const int word = rown[ri] * HROW + w * 4 + tg;
            Nh[word] = hw; Nl[word] = lw;
            if (MODE == 0 && upd) {
                size_t o = ((size_t)offr[ri] + t) * HSZ + u0;
                *(uint32_t*)&g_h0hi[o] = hw;
                *(uint32_t*)&g_h0lo[o] = lw;
            }
        }
        __syncthreads();
        p ^= 1;
    }

    if (MODE == 1) {
        #pragma unroll
        for (int ri = 0; ri < 2; ri++) {
            if (cv) {
                sHF[rown[ri] * HSZ + u0]     = h[ri][0];
                sHF[rown[ri] * HSZ + u0 + 1] = h[ri][1];
            }
        }
        __syncthreads();
        if (tid < MROW) {
            float s = bfc[0];
            #pragma unroll 10
            for (int k = 0; k < HSZ; k++) s += sHF[tid * HSZ + k] * sWf[k];
            out[grow0 + tid] = s;
        }
    }
}

// ===========================================================================
// Kernel G: zpack = h0pack @ Wih1^T + bias1 (fp16x2 split, 2-term)
// ===========================================================================
__global__ void __launch_bounds__(512, 1)
k_gemm_mma(const float* __restrict__ bih1, const float* __restrict__ bhh1)
{
    extern __shared__ char smc[];
    float*   sBias = (float*)smc;                      // 1600
    __half*  sAhi  = (__half*)(smc + 1600);            // 30720
    __half*  sAlo  = (__half*)(smc + 32320);           // 30720
    __half*  sBh   = (__half*)(smc + 63040);           // 53760

    const int tid  = threadIdx.x;
    const int wid  = tid >> 5, lane = tid & 31;
    const int g    = lane >> 2, tg = lane & 3;
    const int wm   = (wid & 3) * 32;
    const int wn   = (wid >> 2) * 56;

    for (int i = tid; i < G4; i += 512) sBias[i] = bih1[i] + bhh1[i];
    for (int i = tid; i < 128 * 20; i += 512) {
        int r = i / 20, kk = 100 + i % 20;
        sAhi[r * LDA + kk] = __float2half(0.f);
        sAlo[r * LDA + kk] = __float2half(0.f);
    }
    for (int i = tid; i < 24 * LDB; i += 512) {
        int r = 200 + i / LDB, kk = i % LDB;
        sBh[r * LDB + kk] = __float2half(0.f);
    }

    const uint32_t aHiB = smem_u32(sAhi) + ((lane & 15) * (LDA/2) + (lane >> 4) * 4) * 4;
    const uint32_t aLoB = smem_u32(sAlo) + ((lane & 15) * (LDA/2) + (lane >> 4) * 4) * 4;

    const int Mpack  = g_off_arr[BSZ];
    const int ntiles = (Mpack + 127) >> 7;
    const int nitems = ntiles * 2;
    int curHalf = -1;

    #pragma unroll 1
    for (int it = blockIdx.x; it < nitems; it += gridDim.x) {
        const int half  = (it >= ntiles) ? 1 : 0;
        const int mtile = it - half * ntiles;
        const size_t m0 = (size_t)mtile << 7;
        const int jo    = half * 200;

        __syncthreads();
        if (half != curHalf) {
            curHalf = half;
            #pragma unroll 1
            for (int i = tid; i < 200 * 14; i += 512) {
                int n = i / 14, kc = (i % 14) * 8;
                size_t go = (size_t)(jo + n) * KP + kc;
                *(uint4*)&sBh[n * LDB + kc] = *(const uint4*)&g_bh[go];
            }
        }
        #pragma unroll 1
        for (int i = tid; i < 128 * 25; i += 512) {
            int r = i / 25, kc = (i % 25) * 4;
            size_t go = (m0 + r) * HSZ + kc;
            *(uint2*)&sAhi[r * LDA + kc] = *(const uint2*)&g_h0hi[go];
            *(uint2*)&sAlo[r * LDA + kc] = *(const uint2*)&g_h0lo[go];
        }
        __syncthreads();

        float D[2][7][4];
        #pragma unroll
        for (int mt = 0; mt < 2; mt++)
            #pragma unroll
            for (int nt = 0; nt < 7; nt++)
                #pragma unroll
                for (int q = 0; q < 4; q++) D[mt][nt][q] = 0.f;

        #pragma unroll
        for (int ks = 0; ks < 7; ks++) {
            uint32_t ahi[2][4], alo[2][4];
            #pragma unroll
            for (int mt = 0; mt < 2; mt++) {
                const uint32_t off = ((wm + mt * 16) * (LDA/2) + ks * 8) * 4;
                ldsm4(ahi[mt], aHiB + off);
                ldsm4(alo[mt], aLoB + off);
            }
            const int kb = ks * 16;
            #pragma unroll
            for (int nt = 0; nt < 7; nt++) {
                const int brow = (wn + nt * 8 + g) * LDB + kb + 2 * tg;
                uint32_t b0 = *(const uint32_t*)&sBh[brow];
                uint32_t b1 = *(const uint32_t*)&sBh[brow + 8];
                #pragma unroll
                for (int mt = 0; mt < 2; mt++) {
                    mma_fp16(D[mt][nt], ahi[mt], b0, b1);
                    mma_fp16(D[mt][nt], alo[mt], b0, b1);
                }
            }
        }

        #pragma unroll
        for (int mt = 0; mt < 2; mt++) {
            #pragma unroll
            for (int nt = 0; nt < 7; nt++) {
                int n_rel = wn + nt * 8 + 2 * tg;
                if (n_rel < 200) {
                    int ncol = jo + n_rel;
                    float b0v = sBias[ncol], b1v = sBias[ncol + 1];
                    size_t R = m0 + wm + mt * 16 + g;
                    if (R < (size_t)Mpack) {
                        float2 v = make_float2(D[mt][nt][0] + b0v, D[mt][nt][1] + b1v);
                        *(float2*)&g_zpack[R * G4 + ncol] = v;
                    }
                    if (R + 8 < (size_t)Mpack) {
                        float2 v = make_float2(D[mt][nt][2] + b0v, D[mt][nt][3] + b1v);
                        *(float2*)&g_zpack[(R + 8) * G4 + ncol] = v;
                    }
                }
            }
        }
    }
}

// ===========================================================================
// Launch
// ===========================================================================
extern "C" void kernel_launch(void* const* d_in, const int* in_sizes, int n_in,
                              void* d_out, int out_size)
{
    const float* x       = (const float*)d_in[0];
    const int*   lengths = (const int*)  d_in[1];
    const float* Wih0    = (const float*)d_in[2];
    const float* Whh0    = (const float*)d_in[3];
    const float* bih0    = (const float*)d_in[4];
    const float* bhh0    = (const float*)d_in[5];
    const float* Wih1    = (const float*)d_in[6];
    const float* Whh1    = (const float*)d_in[7];
    const float* bih1    = (const float*)d_in[8];
    const float* bhh1    = (const float*)d_in[9];
    const float* Wfc     = (const float*)d_in[10];
    const float* bfc     = (const float*)d_in[11];
    float* out = (float*)d_out;

    uint32_t *w2h0, *w2h1;
    cudaGetSymbolAddress((void**)&w2h0, g_w2h0);
    cudaGetSymbolAddress((void**)&w2h1, g_w2h1);

    const int smG = 1600 + 2 * 30720 + 53760;   // 116,800
    const int smR = 111232;                      // 2 CTAs/SM -> 222,464 B

    cudaFuncSetAttribute(k_gemm_mma, cudaFuncAttributeMaxDynamicSharedMemorySize, smG);
    cudaFuncSetAttribute(k_rec<0>,   cudaFuncAttributeMaxDynamicSharedMemorySize, smR);
    cudaFuncSetAttribute(k_rec<1>,   cudaFuncAttributeMaxDynamicSharedMemorySize, smR);

    const int gridR = BSZ / MROW;   // 256
    k_scan  <<<1, 512>>>(lengths);
    k_wsplit<<<(G4 * KP + 255) / 256, 256>>>(Wih1);
    k_wprep <<<(W2N + 255) / 256, 256>>>(Whh0, w2h0);
    k_wprep <<<(W2N + 255) / 256, 256>>>(Whh1, w2h1);
    k_zx0   <<<128, 512>>>(x, lengths, Wih0, bih0, bhh0);
    k_rec<0><<<gridR, RTH, smR>>>(lengths, nullptr, nullptr, nullptr);
    k_gemm_mma<<<148, 512, smG>>>(bih1, bhh1);
    k_rec<1><<<gridR, RTH, smR>>>(lengths, Wfc, bfc, out);
}

// round 13
// speedup vs baseline: 1.3903x; 1.3903x over previous
#include <cuda_runtime.h>
#include <cuda_fp16.h>
#include <cstdint>
#include <cstddef>

// Problem constants
#define BSZ 4096
#define TSZ 100
#define FSZ 13
#define HSZ 100
#define G4  400

// GEMM constants
#define KP   112
#define LDA  120
#define LDB  120

// Recurrent kernel constants
#define RW    13
#define RTH   (RW*32)
#define W2N   23296         // W fragment words (52 ntiles * 7 kt * 64)
#define HROW  68            // h row stride in words
#define MROW  16            // batch rows per CTA (sorted by length)
#define HBUFW (MROW*HROW)   // 1088 words per buffer

// ---------------------------------------------------------------------------
// Scratch (device globals)
// ---------------------------------------------------------------------------
__device__ __half g_h0hi[(size_t)BSZ * TSZ * HSZ];
__device__ __half g_h0lo[(size_t)BSZ * TSZ * HSZ];
__device__ __half g_bh[G4 * KP];                  // W_ih1 fp16 (gemm layout)
__device__ float g_zpack [(size_t)BSZ * TSZ * G4];
__device__ float g_z0pack[(size_t)BSZ * TSZ * G4];
__device__ int   g_off_arr[BSZ + 1];
__device__ int   g_perm[BSZ];                     // rows sorted by length desc
__device__ uint32_t g_w2h0[W2N];                  // Whh0 fp16 frag layout
__device__ uint32_t g_w2h1[W2N];                  // Whh1 fp16 frag layout

// ---------------------------------------------------------------------------
// Helpers
// ---------------------------------------------------------------------------
__device__ __forceinline__ float tanha(float x) {
    float y;
    asm("tanh.approx.f32 %0, %1;" : "=f"(y) : "f"(x));
    return y;
}
__device__ __forceinline__ float siga(float x) {
    return fmaf(0.5f, tanha(0.5f * x), 0.5f);
}
__device__ __forceinline__ void ffma2(unsigned long long &d,
                                      unsigned long long a,
                                      unsigned long long b) {
    asm("fma.rn.f32x2 %0, %1, %2, %0;" : "+l"(d) : "l"(a), "l"(b));
}
__device__ __forceinline__ unsigned long long pk(float lo, float hi) {
    unsigned long long r;
    asm("mov.b64 %0, {%1, %2};" : "=l"(r) : "f"(lo), "f"(hi));
    return r;
}
__device__ __forceinline__ float psum(unsigned long long a) {
    float lo = __uint_as_float((unsigned)(a & 0xffffffffull));
    float hi = __uint_as_float((unsigned)(a >> 32));
    return lo + hi;
}
__device__ __forceinline__ void mma_fp16(float* d, const uint32_t* a,
                                         uint32_t b0, uint32_t b1) {
    asm volatile(
        "mma.sync.aligned.m16n8k16.row.col.f32.f16.f16.f32 "
        "{%0,%1,%2,%3}, {%4,%5,%6,%7}, {%8,%9}, {%0,%1,%2,%3};"
        : "+f"(d[0]), "+f"(d[1]), "+f"(d[2]), "+f"(d[3])
        : "r"(a[0]), "r"(a[1]), "r"(a[2]), "r"(a[3]), "r"(b0), "r"(b1));
}
__device__ __forceinline__ void ldsm4(uint32_t* r, uint32_t addr) {
    asm volatile("ldmatrix.sync.aligned.m8n8.x4.shared.b16 {%0,%1,%2,%3}, [%4];"
        : "=r"(r[0]), "=r"(r[1]), "=r"(r[2]), "=r"(r[3]) : "r"(addr));
}
__device__ __forceinline__ uint32_t smem_u32(const void* p) {
    uint32_t a;
    asm("{ .reg .u64 t; cvta.to.shared.u64 t, %1; cvt.u32.u64 %0, t; }"
        : "=r"(a) : "l"(p));
    return a;
}
__device__ __forceinline__ void split_h2(float f0, float f1,
                                         uint32_t &hw, uint32_t &lw) {
    __half2 h2 = __float22half2_rn(make_float2(f0, f1));
    hw = *(uint32_t*)&h2;
    float2 back = __half22float2(h2);
    __half2 l2 = __float22half2_rn(make_float2(f0 - back.x, f1 - back.y));
    lw = *(uint32_t*)&l2;
}

// ===========================================================================
// Kernel S: exclusive prefix scan of lengths (1 CTA)
// ===========================================================================
__global__ void __launch_bounds__(512, 1) k_scan(const int* __restrict__ lengths)
{
    __shared__ int s[512];
    const int tid = threadIdx.x;
    const int base = tid * 8;
    int v[8]; int loc = 0;
    #pragma unroll
    for (int i = 0; i < 8; i++) { v[i] = lengths[base + i]; loc += v[i]; }
    s[tid] = loc;
    __syncthreads();
    for (int d = 1; d < 512; d <<= 1) {
        int t = (tid >= d) ? s[tid - d] : 0;
        __syncthreads();
        s[tid] += t;
        __syncthreads();
    }
    int run = s[tid] - loc;
    #pragma unroll
    for (int i = 0; i < 8; i++) { g_off_arr[base + i] = run; run += v[i]; }
    if (tid == 511) g_off_arr[BSZ] = s[511];
}

// ===========================================================================
// Kernel P: counting sort of rows by length (descending) -> g_perm
//   (tie order nondeterministic, but per-row outputs are independent of
//    assignment, so the kernel output is bitwise deterministic)
// ===========================================================================
__global__ void __launch_bounds__(512, 1) k_sortperm(const int* __restrict__ lengths)
{
    __shared__ int bins[101];
    const int tid = threadIdx.x;
    if (tid < 101) bins[tid] = 0;
    __syncthreads();
    for (int i = tid; i < BSZ; i += 512)
        atomicAdd(&bins[100 - lengths[i]], 1);   // key = 100-len (descending)
    __syncthreads();
    if (tid == 0) {                               // small exclusive scan
        int run = 0;
        for (int k = 0; k <= 100; k++) { int c = bins[k]; bins[k] = run; run += c; }
    }
    __syncthreads();
    for (int i = tid; i < BSZ; i += 512) {
        int pos = atomicAdd(&bins[100 - lengths[i]], 1);
        g_perm[pos] = i;
    }
}

// ===========================================================================
// Kernel W1: W_ih1 -> fp16 (gemm layout, k-padded)
// ===========================================================================
__global__ void __launch_bounds__(256, 1) k_wsplit(const float* __restrict__ Wih1)
{
    int idx = blockIdx.x * 256 + threadIdx.x;
    if (idx < G4 * KP) {
        int n = idx / KP, k = idx % KP;
        float v = (k < HSZ) ? Wih1[n * HSZ + k] : 0.f;
        g_bh[idx] = __float2half(v);
    }
}

// ===========================================================================
// Kernel W2: Whh -> fp16 pair-packed fragment layout
// ===========================================================================
__global__ void __launch_bounds__(256, 1)
k_wprep(const float* __restrict__ W, uint32_t* __restrict__ dh)
{
    int j = blockIdx.x * 256 + threadIdx.x;
    if (j >= W2N) return;
    int sel = j & 1;
    int pp  = (j >> 1) & 31;
    int tg  = pp >> 3, g = pp & 7;
    int grp = j >> 6;
    int kt  = grp % 7, n = grp / 7;
    int row = n * 8 + g;
    int gate = row / 104, u = row % 104;
    int k    = kt * 16 + 2 * tg + 8 * sel;
    float f0 = (u < HSZ && k     < HSZ) ? W[(gate * HSZ + u) * HSZ + k]     : 0.f;
    float f1 = (u < HSZ && k + 1 < HSZ) ? W[(gate * HSZ + u) * HSZ + k + 1] : 0.f;
    __half2 h2 = __float22half2_rn(make_float2(f0, f1));
    dh[j] = *(uint32_t*)&h2;
}

// ===========================================================================
// Kernel Z0: g_z0pack = bias0 + x @ Wih0^T (packed rows, fp32)
// ===========================================================================
__global__ void __launch_bounds__(512, 1)
k_zx0(const float* __restrict__ x, const int* __restrict__ lengths,
      const float* __restrict__ Wih0,
      const float* __restrict__ bih0, const float* __restrict__ bhh0)
{
    __shared__ float sX[1400];
    __shared__ int sLen[32], sOff[32];
    const int tid = threadIdx.x;
    const int grow0 = blockIdx.x * 32;
    if (tid < 32) {
        sLen[tid] = lengths[grow0 + tid];
        sOff[tid] = g_off_arr[grow0 + tid];
    }
    const int u = tid;
    const bool act = (u < G4);
    unsigned long long wp[7];
    float b = 0.f;
    if (act) {
        float wr[14];
        #pragma unroll
        for (int k = 0; k < FSZ; k++) wr[k] = Wih0[u * FSZ + k];
        wr[13] = 0.f;
        #pragma unroll
        for (int i = 0; i < 7; i++) wp[i] = pk(wr[2*i], wr[2*i+1]);
        b = bih0[u] + bhh0[u];
    }
    __syncthreads();

    for (int r = 0; r < 32; r++) {
        const int len = sLen[r], off = sOff[r];
        __syncthreads();
        const float* xs = x + (size_t)(grow0 + r) * (TSZ * FSZ);
        for (int i = tid; i < 1400; i += 512) {
            int t = i / 14, k = i % 14;
            sX[i] = (k < FSZ) ? xs[t * FSZ + k] : 0.f;
        }
        __syncthreads();
        if (act) {
            for (int t = 0; t < len; t++) {
                unsigned long long acc = pk(b, 0.f);
                #pragma unroll
                for (int kp = 0; kp < 7; kp++)
                    ffma2(acc, wp[kp], *(const unsigned long long*)&sX[t*14 + 2*kp]);
                g_z0pack[(size_t)(off + t) * G4 + u] = psum(acc);
            }
        }
    }
}

// ===========================================================================
// Kernel R: fp16x2 tensor LSTM — R8 recipe, M=16 length-sorted rows per CTA
// ===========================================================================
template<int MODE>
__global__ void __launch_bounds__(RTH, 1)
k_rec(const int* __restrict__ lengths,
      const float* __restrict__ Wfc, const float* __restrict__ bfc,
      float* __restrict__ out)
{
    extern __shared__ char smc[];
    uint32_t* sW   = (uint32_t*)(smc);                 // 93184 B
    uint32_t* sHhi = (uint32_t*)(smc + 93184);         // 2 x 4352 B
    uint32_t* sHlo = (uint32_t*)(smc + 101888);        // 2 x 4352 B
    int*   sLen  = (int*)(smc + 110592);               // 16
    int*   sOff  = (int*)(smc + 110656);               // 16
    int*   sPerm = (int*)(smc + 110720);               // 16
    float* sWf   = (float*)(smc + 110784);             // 100 floats
    float* sHF   = (float*)(smc + 93184);              // fc reuse (after loop)

    const uint32_t* gw   = MODE ? g_w2h1 : g_w2h0;
    const float*    zsrc = MODE ? g_zpack : g_z0pack;

    const int tid = threadIdx.x;
    const int srow0 = blockIdx.x * MROW;

    for (int i = tid; i < W2N; i += RTH) sW[i] = gw[i];
    for (int i = tid; i < 2 * HBUFW; i += RTH) { sHhi[i] = 0u; sHlo[i] = 0u; }
    if (tid < MROW) {
        int orow = g_perm[srow0 + tid];
        sPerm[tid] = orow;
        sLen[tid]  = lengths[orow];
        sOff[tid]  = g_off_arr[orow];
    }
    if (MODE == 1 && tid < HSZ) sWf[tid] = Wfc[tid];
    __syncthreads();

    int Lmax = 0;
    #pragma unroll
    for (int r = 0; r < MROW; r++) Lmax = max(Lmax, sLen[r]);

    const int w = tid >> 5, lane = tid & 31;
    const int g = lane >> 2, tg = lane & 3;
    const int u0 = w * 8 + 2 * tg;
    const bool cv = (u0 < HSZ);

    const uint32_t sb = smem_u32(smc);
    const uint32_t lmoff = ((lane & 15) * HROW + (lane >> 4) * 4) * 4;
    const uint32_t hHiB = sb + 93184 + lmoff;
    const uint32_t hLoB = sb + 101888 + lmoff;

    int rown[2], lenr[2], offr[2];
    #pragma unroll
    for (int ri = 0; ri < 2; ri++) {
        rown[ri] = ri * 8 + g;
        lenr[ri] = sLen[rown[ri]];
        offr[ri] = sOff[rown[ri]];
    }
    float c[2][2] = {{0.f,0.f},{0.f,0.f}};
    float h[2][2] = {{0.f,0.f},{0.f,0.f}};

    int p = 0;
    #pragma unroll 1
    for (int t = 0; t < Lmax; t++) {
        // z(t) prefetch (LDG issued first, consumed after the MMA block)
        float2 zn[2][4];
        #pragma unroll
        for (int ri = 0; ri < 2; ri++) {
            const bool lv = cv && (t < lenr[ri]);
            const size_t zb = (size_t)(offr[ri] + t) * G4;
            #pragma unroll
            for (int G = 0; G < 4; G++)
                zn[ri][G] = lv ? *(const float2*)&zsrc[zb + G * HSZ + u0]
                               : make_float2(0.f, 0.f);
        }

        float D[4][4];
        #pragma unroll
        for (int G = 0; G < 4; G++)
            #pragma unroll
            for (int q = 0; q < 4; q++) D[G][q] = 0.f;

        const uint32_t hHi = hHiB + p * 4352;
        const uint32_t hLo = hLoB + p * 4352;
        #pragma unroll
        for (int kt = 0; kt < 7; kt++) {
            uint32_t ahi[4], alo[4];
            ldsm4(ahi, hHi + kt * 32);
            ldsm4(alo, hLo + kt * 32);
            #pragma unroll
            for (int G = 0; G < 4; G++) {
                const int b2 = (((G * 13 + w) * 7 + kt) * 32 + tg * 8 + g) * 2;
                uint2 bh = *(const uint2*)&sW[b2];
                mma_fp16(D[G], ahi, bh.x, bh.y);
                mma_fp16(D[G], alo, bh.x, bh.y);
            }
        }

        // activation + state update + stage h(t+1) into buffer 1-p
        uint32_t* Nh = sHhi + (1 - p) * HBUFW;
        uint32_t* Nl = sHlo + (1 - p) * HBUFW;
        #pragma unroll
        for (int ri = 0; ri < 2; ri++) {
            const bool upd = cv && (t < lenr[ri]);
            #pragma unroll
            for (int j = 0; j < 2; j++) {
                float zi = D[0][ri * 2 + j] + (j ? zn[ri][0].y : zn[ri][0].x);
                float zf = D[1][ri * 2 + j] + (j ? zn[ri][1].y : zn[ri][1].x);
                float zg = D[2][ri * 2 + j] + (j ? zn[ri][2].y : zn[ri][2].x);
                float zo = D[3][ri * 2 + j] + (j ? zn[ri][3].y : zn[ri][3].x);
                float cn = siga(zf) * c[ri][j] + siga(zi) * tanha(zg);
                float hn = siga(zo) * tanha(cn);
                if (upd) { c[ri][j] = cn; h[ri][j] = hn; }
            }
            uint32_t hw, lw;
            split_h2(h[ri][0], h[ri][1], hw, lw);
            const int word = rown[ri] * HROW + w * 4 + tg;
            Nh[word] = hw; Nl[word] = lw;
            if (MODE == 0 && upd) {
                size_t o = ((size_t)offr[ri] + t) * HSZ + u0;
                *(uint32_t*)&g_h0hi[o] = hw;
                *(uint32_t*)&g_h0lo[o] = lw;
            }
        }
        __syncthreads();
        p ^= 1;
    }

    if (MODE == 1) {
        #pragma unroll
        for (int ri = 0; ri < 2; ri++) {
            if (cv) {
                sHF[rown[ri] * HSZ + u0]     = h[ri][0];
                sHF[rown[ri] * HSZ + u0 + 1] = h[ri][1];
            }
        }
        __syncthreads();
        if (tid < MROW) {
            float s = bfc[0];
            #pragma unroll 10
            for (int k = 0; k < HSZ; k++) s += sHF[tid * HSZ + k] * sWf[k];
            out[sPerm[tid]] = s;
        }
    }
}

// ===========================================================================
// Kernel G: zpack = h0pack @ Wih1^T + bias1 (fp16x2 split, 2-term)
// ===========================================================================
__global__ void __launch_bounds__(512, 1)
k_gemm_mma(const float* __restrict__ bih1, const float* __restrict__ bhh1)
{
    extern __shared__ char smc[];
    float*   sBias = (float*)smc;                      // 1600
    __half*  sAhi  = (__half*)(smc + 1600);            // 30720
    __half*  sAlo  = (__half*)(smc + 32320);           // 30720
    __half*  sBh   = (__half*)(smc + 63040);           // 53760

    const int tid  = threadIdx.x;
    const int wid  = tid >> 5, lane = tid & 31;
    const int g    = lane >> 2, tg = lane & 3;
    const int wm   = (wid & 3) * 32;
    const int wn   = (wid >> 2) * 56;

    for (int i = tid; i < G4; i += 512) sBias[i] = bih1[i] + bhh1[i];
    for (int i = tid; i < 128 * 20; i += 512) {
        int r = i / 20, kk = 100 + i % 20;
        sAhi[r * LDA + kk] = __float2half(0.f);
        sAlo[r * LDA + kk] = __float2half(0.f);
    }
    for (int i = tid; i < 24 * LDB; i += 512) {
        int r = 200 + i / LDB, kk = i % LDB;
        sBh[r * LDB + kk] = __float2half(0.f);
    }

    const uint32_t aHiB = smem_u32(sAhi) + ((lane & 15) * (LDA/2) + (lane >> 4) * 4) * 4;
    const uint32_t aLoB = smem_u32(sAlo) + ((lane & 15) * (LDA/2) + (lane >> 4) * 4) * 4;

    const int Mpack  = g_off_arr[BSZ];
    const int ntiles = (Mpack + 127) >> 7;
    const int nitems = ntiles * 2;
    int curHalf = -1;

    #pragma unroll 1
    for (int it = blockIdx.x; it < nitems; it += gridDim.x) {
        const int half  = (it >= ntiles) ? 1 : 0;
        const int mtile = it - half * ntiles;
        const size_t m0 = (size_t)mtile << 7;
        const int jo    = half * 200;

        __syncthreads();
        if (half != curHalf) {
            curHalf = half;
            #pragma unroll 1
            for (int i = tid; i < 200 * 14; i += 512) {
                int n = i / 14, kc = (i % 14) * 8;
                size_t go = (size_t)(jo + n) * KP + kc;
                *(uint4*)&sBh[n * LDB + kc] = *(const uint4*)&g_bh[go];
            }
        }
        #pragma unroll 1
        for (int i = tid; i < 128 * 25; i += 512) {
            int r = i / 25, kc = (i % 25) * 4;
            size_t go = (m0 + r) * HSZ + kc;
            *(uint2*)&sAhi[r * LDA + kc] = *(const uint2*)&g_h0hi[go];
            *(uint2*)&sAlo[r * LDA + kc] = *(const uint2*)&g_h0lo[go];
        }
        __syncthreads();

        float D[2][7][4];
        #pragma unroll
        for (int mt = 0; mt < 2; mt++)
            #pragma unroll
            for (int nt = 0; nt < 7; nt++)
                #pragma unroll
                for (int q = 0; q < 4; q++) D[mt][nt][q] = 0.f;

        #pragma unroll
        for (int ks = 0; ks < 7; ks++) {
            uint32_t ahi[2][4], alo[2][4];
            #pragma unroll
            for (int mt = 0; mt < 2; mt++) {
                const uint32_t off = ((wm + mt * 16) * (LDA/2) + ks * 8) * 4;
                ldsm4(ahi[mt], aHiB + off);
                ldsm4(alo[mt], aLoB + off);
            }
            const int kb = ks * 16;
            #pragma unroll
            for (int nt = 0; nt < 7; nt++) {
                const int brow = (wn + nt * 8 + g) * LDB + kb + 2 * tg;
                uint32_t b0 = *(const uint32_t*)&sBh[brow];
                uint32_t b1 = *(const uint32_t*)&sBh[brow + 8];
                #pragma unroll
                for (int mt = 0; mt < 2; mt++) {
                    mma_fp16(D[mt][nt], ahi[mt], b0, b1);
                    mma_fp16(D[mt][nt], alo[mt], b0, b1);
                }
            }
        }

        #pragma unroll
        for (int mt = 0; mt < 2; mt++) {
            #pragma unroll
            for (int nt = 0; nt < 7; nt++) {
                int n_rel = wn + nt * 8 + 2 * tg;
                if (n_rel < 200) {
                    int ncol = jo + n_rel;
                    float b0v = sBias[ncol], b1v = sBias[ncol + 1];
                    size_t R = m0 + wm + mt * 16 + g;
                    if (R < (size_t)Mpack) {
                        float2 v = make_float2(D[mt][nt][0] + b0v, D[mt][nt][1] + b1v);
                        *(float2*)&g_zpack[R * G4 + ncol] = v;
                    }
                    if (R + 8 < (size_t)Mpack) {
                        float2 v = make_float2(D[mt][nt][2] + b0v, D[mt][nt][3] + b1v);
                        *(float2*)&g_zpack[(R + 8) * G4 + ncol] = v;
                    }
                }
            }
        }
    }
}

// ===========================================================================
// Launch
// ===========================================================================
extern "C" void kernel_launch(void* const* d_in, const int* in_sizes, int n_in,
                              void* d_out, int out_size)
{
    const float* x       = (const float*)d_in[0];
    const int*   lengths = (const int*)  d_in[1];
    const float* Wih0    = (const float*)d_in[2];
    const float* Whh0    = (const float*)d_in[3];
    const float* bih0    = (const float*)d_in[4];
    const float* bhh0    = (const float*)d_in[5];
    const float* Wih1    = (const float*)d_in[6];
    const float* Whh1    = (const float*)d_in[7];
    const float* bih1    = (const float*)d_in[8];
    const float* bhh1    = (const float*)d_in[9];
    const float* Wfc     = (const float*)d_in[10];
    const float* bfc     = (const float*)d_in[11];
    float* out = (float*)d_out;

    uint32_t *w2h0, *w2h1;
    cudaGetSymbolAddress((void**)&w2h0, g_w2h0);
    cudaGetSymbolAddress((void**)&w2h1, g_w2h1);

    const int smG = 1600 + 2 * 30720 + 53760;   // 116,800
    const int smR = 111232;

    cudaFuncSetAttribute(k_gemm_mma, cudaFuncAttributeMaxDynamicSharedMemorySize, smG);
    cudaFuncSetAttribute(k_rec<0>,   cudaFuncAttributeMaxDynamicSharedMemorySize, smR);
    cudaFuncSetAttribute(k_rec<1>,   cudaFuncAttributeMaxDynamicSharedMemorySize, smR);

    const int gridR = BSZ / MROW;   // 256 CTAs, longest first
    k_scan    <<<1, 512>>>(lengths);
    k_sortperm<<<1, 512>>>(lengths);
    k_wsplit  <<<(G4 * KP + 255) / 256, 256>>>(Wih1);
    k_wprep   <<<(W2N + 255) / 256, 256>>>(Whh0, w2h0);
    k_wprep   <<<(W2N + 255) / 256, 256>>>(Whh1, w2h1);
    k_zx0     <<<128, 512>>>(x, lengths, Wih0, bih0, bhh0);
    k_rec<0>  <<<gridR, RTH, smR>>>(lengths, nullptr, nullptr, nullptr);
    k_gemm_mma<<<148, 512, smG>>>(bih1, bhh1);
    k_rec<1>  <<<gridR, RTH, smR>>>(lengths, Wfc, bfc, out);
}

// round 14
// speedup vs baseline: 1.6496x; 1.1865x over previous
#include <cuda_runtime.h>
#include <cuda_fp16.h>
#include <cstdint>
#include <cstddef>

// Problem constants
#define BSZ 4096
#define TSZ 100
#define FSZ 13
#define HSZ 100
#define G4  400

// Recurrent/fused kernel constants
#define RW    13
#define RTH   (RW*32)
#define W2N   23296         // W fragment words (52 ntiles * 7 kt * 64)
#define HROW  68            // h row stride in words (ldmatrix conflict-free)
#define MROW  16            // batch rows per CTA (sorted by length)
#define HBUFW (MROW*HROW)   // 1088 words per single buffer

// SMEM byte offsets (fused kernel)
#define OFF_WI   0           // Wih1 frags   93184
#define OFF_WH   93184       // Whh1 frags   93184
#define OFF_H0HI 186368      // 2 x 4352
#define OFF_H0LO 195072
#define OFF_H1HI 203776
#define OFF_H1LO 212480
#define OFF_LEN  221184
#define OFF_OFFA 221248
#define OFF_PERM 221312
#define OFF_B1   221376      // 400 floats
#define OFF_WF   222976      // 100 floats
#define SMR      223488

// ---------------------------------------------------------------------------
// Scratch (device globals)
// ---------------------------------------------------------------------------
__device__ float g_z0pack[(size_t)BSZ * TSZ * G4];   // layer-0 z (bias0 + Wx)
__device__ int   g_off_arr[BSZ + 1];
__device__ int   g_perm[BSZ];                        // rows sorted by len desc
__device__ uint32_t g_w2h0[W2N];                     // Whh0 frag layout
__device__ uint32_t g_w2h1[W2N];                     // Whh1 frag layout
__device__ uint32_t g_w2i1[W2N];                     // Wih1 frag layout

// ---------------------------------------------------------------------------
// Helpers
// ---------------------------------------------------------------------------
__device__ __forceinline__ float tanha(float x) {
    float y;
    asm("tanh.approx.f32 %0, %1;" : "=f"(y) : "f"(x));
    return y;
}
__device__ __forceinline__ float siga(float x) {
    return fmaf(0.5f, tanha(0.5f * x), 0.5f);
}
__device__ __forceinline__ void ffma2(unsigned long long &d,
                                      unsigned long long a,
                                      unsigned long long b) {
    asm("fma.rn.f32x2 %0, %1, %2, %0;" : "+l"(d) : "l"(a), "l"(b));
}
__device__ __forceinline__ unsigned long long pk(float lo, float hi) {
    unsigned long long r;
    asm("mov.b64 %0, {%1, %2};" : "=l"(r) : "f"(lo), "f"(hi));
    return r;
}
__device__ __forceinline__ float psum(unsigned long long a) {
    float lo = __uint_as_float((unsigned)(a & 0xffffffffull));
    float hi = __uint_as_float((unsigned)(a >> 32));
    return lo + hi;
}
__device__ __forceinline__ void mma_fp16(float* d, const uint32_t* a,
                                         uint32_t b0, uint32_t b1) {
    asm volatile(
        "mma.sync.aligned.m16n8k16.row.col.f32.f16.f16.f32 "
        "{%0,%1,%2,%3}, {%4,%5,%6,%7}, {%8,%9}, {%0,%1,%2,%3};"
        : "+f"(d[0]), "+f"(d[1]), "+f"(d[2]), "+f"(d[3])
        : "r"(a[0]), "r"(a[1]), "r"(a[2]), "r"(a[3]), "r"(b0), "r"(b1));
}
__device__ __forceinline__ void ldsm4(uint32_t* r, uint32_t addr) {
    asm volatile("ldmatrix.sync.aligned.m8n8.x4.shared.b16 {%0,%1,%2,%3}, [%4];"
        : "=r"(r[0]), "=r"(r[1]), "=r"(r[2]), "=r"(r[3]) : "r"(addr));
}
__device__ __forceinline__ uint32_t smem_u32(const void* p) {
    uint32_t a;
    asm("{ .reg .u64 t; cvta.to.shared.u64 t, %1; cvt.u32.u64 %0, t; }"
        : "=r"(a) : "l"(p));
    return a;
}
__device__ __forceinline__ void split_h2(float f0, float f1,
                                         uint32_t &hw, uint32_t &lw) {
    __half2 h2 = __float22half2_rn(make_float2(f0, f1));
    hw = *(uint32_t*)&h2;
    float2 back = __half22float2(h2);
    __half2 l2 = __float22half2_rn(make_float2(f0 - back.x, f1 - back.y));
    lw = *(uint32_t*)&l2;
}

// ===========================================================================
// Kernel S: exclusive prefix scan of lengths (1 CTA)
// ===========================================================================
__global__ void __launch_bounds__(512, 1) k_scan(const int* __restrict__ lengths)
{
    __shared__ int s[512];
    const int tid = threadIdx.x;
    const int base = tid * 8;
    int v[8]; int loc = 0;
    #pragma unroll
    for (int i = 0; i < 8; i++) { v[i] = lengths[base + i]; loc += v[i]; }
    s[tid] = loc;
    __syncthreads();
    for (int d = 1; d < 512; d <<= 1) {
        int t = (tid >= d) ? s[tid - d] : 0;
        __syncthreads();
        s[tid] += t;
        __syncthreads();
    }
    int run = s[tid] - loc;
    #pragma unroll
    for (int i = 0; i < 8; i++) { g_off_arr[base + i] = run; run += v[i]; }
    if (tid == 511) g_off_arr[BSZ] = s[511];
}

// ===========================================================================
// Kernel P: counting sort by length (descending) -> g_perm
// ===========================================================================
__global__ void __launch_bounds__(512, 1) k_sortperm(const int* __restrict__ lengths)
{
    __shared__ int bins[101];
    const int tid = threadIdx.x;
    if (tid < 101) bins[tid] = 0;
    __syncthreads();
    for (int i = tid; i < BSZ; i += 512)
        atomicAdd(&bins[100 - lengths[i]], 1);
    __syncthreads();
    if (tid == 0) {
        int run = 0;
        for (int k = 0; k <= 100; k++) { int c = bins[k]; bins[k] = run; run += c; }
    }
    __syncthreads();
    for (int i = tid; i < BSZ; i += 512) {
        int pos = atomicAdd(&bins[100 - lengths[i]], 1);
        g_perm[pos] = i;
    }
}

// ===========================================================================
// Kernel W: W[400][100] -> fp16 pair-packed fragment layout (generic)
//   grid.y selects which (src, dst) pair when launched doubled
// ===========================================================================
__device__ __forceinline__ void wprep_one(const float* __restrict__ W,
                                          uint32_t* __restrict__ dh, int j)
{
    int sel = j & 1;
    int pp  = (j >> 1) & 31;
    int tg  = pp >> 3, g = pp & 7;
    int grp = j >> 6;
    int kt  = grp % 7, n = grp / 7;
    int row = n * 8 + g;
    int gate = row / 104, u = row % 104;
    int k    = kt * 16 + 2 * tg + 8 * sel;
    float f0 = (u < HSZ && k     < HSZ) ? W[(gate * HSZ + u) * HSZ + k]     : 0.f;
    float f1 = (u < HSZ && k + 1 < HSZ) ? W[(gate * HSZ + u) * HSZ + k + 1] : 0.f;
    __half2 h2 = __float22half2_rn(make_float2(f0, f1));
    dh[j] = *(uint32_t*)&h2;
}

__global__ void __launch_bounds__(256, 1)
k_wprep2(const float* __restrict__ W0, const float* __restrict__ W1)
{
    int j = blockIdx.x * 256 + threadIdx.x;
    if (j >= W2N) return;
    if (blockIdx.y == 0) wprep_one(W0, g_w2h0, j);
    else                 wprep_one(W1, g_w2h1, j);
}

__global__ void __launch_bounds__(256, 1)
k_wprep1(const float* __restrict__ W)
{
    int j = blockIdx.x * 256 + threadIdx.x;
    if (j >= W2N) return;
    wprep_one(W, g_w2i1, j);
}

// ===========================================================================
// Kernel Z0: g_z0pack = bias0 + x @ Wih0^T (packed rows, fp32)
// ===========================================================================
__global__ void __launch_bounds__(512, 1)
k_zx0(const float* __restrict__ x, const int* __restrict__ lengths,
      const float* __restrict__ Wih0,
      const float* __restrict__ bih0, const float* __restrict__ bhh0)
{
    __shared__ float sX[1400];
    __shared__ int sLen[32], sOff[32];
    const int tid = threadIdx.x;
    const int grow0 = blockIdx.x * 32;
    if (tid < 32) {
        sLen[tid] = lengths[grow0 + tid];
        sOff[tid] = g_off_arr[grow0 + tid];
    }
    const int u = tid;
    const bool act = (u < G4);
    unsigned long long wp[7];
    float b = 0.f;
    if (act) {
        float wr[14];
        #pragma unroll
        for (int k = 0; k < FSZ; k++) wr[k] = Wih0[u * FSZ + k];
        wr[13] = 0.f;
        #pragma unroll
        for (int i = 0; i < 7; i++) wp[i] = pk(wr[2*i], wr[2*i+1]);
        b = bih0[u] + bhh0[u];
    }
    __syncthreads();

    for (int r = 0; r < 32; r++) {
        const int len = sLen[r], off = sOff[r];
        __syncthreads();
        const float* xs = x + (size_t)(grow0 + r) * (TSZ * FSZ);
        for (int i = tid; i < 1400; i += 512) {
            int t = i / 14, k = i % 14;
            sX[i] = (k < FSZ) ? xs[t * FSZ + k] : 0.f;
        }
        __syncthreads();
        if (act) {
            for (int t = 0; t < len; t++) {
                unsigned long long acc = pk(b, 0.f);
                #pragma unroll
                for (int kp = 0; kp < 7; kp++)
                    ffma2(acc, wp[kp], *(const unsigned long long*)&sX[t*14 + 2*kp]);
                g_z0pack[(size_t)(off + t) * G4 + u] = psum(acc);
            }
        }
    }
}

// ===========================================================================
// Kernel F: FUSED 2-layer LSTM, 16 length-sorted rows per CTA
//   per step: MMA-L0 (Whh0 in regs) -> act0 -> bar ->
//             MMA-L1 (Wih1 x h0(t) + Whh1 x h1(t-1), frags in SMEM) ->
//             act1(+bias1) -> bar
// ===========================================================================
__global__ void __launch_bounds__(RTH, 1)
k_fused(const int* __restrict__ lengths,
        const float* __restrict__ bih1, const float* __restrict__ bhh1,
        const float* __restrict__ Wfc, const float* __restrict__ bfc,
        float* __restrict__ out)
{
    extern __shared__ char smc[];
    uint32_t* sWi   = (uint32_t*)(smc + OFF_WI);
    uint32_t* sWh   = (uint32_t*)(smc + OFF_WH);
    uint32_t* sH0hi = (uint32_t*)(smc + OFF_H0HI);
    uint32_t* sH0lo = (uint32_t*)(smc + OFF_H0LO);
    uint32_t* sH1hi = (uint32_t*)(smc + OFF_H1HI);
    uint32_t* sH1lo = (uint32_t*)(smc + OFF_H1LO);
    int*   sLen  = (int*)(smc + OFF_LEN);
    int*   sOff  = (int*)(smc + OFF_OFFA);
    int*   sPerm = (int*)(smc + OFF_PERM);
    float* sB1   = (float*)(smc + OFF_B1);
    float* sWf   = (float*)(smc + OFF_WF);
    float* sHF   = (float*)smc;     // fc staging, reused after loop

    const int tid = threadIdx.x;
    const int srow0 = blockIdx.x * MROW;

    for (int i = tid; i < W2N; i += RTH) { sWi[i] = g_w2i1[i]; sWh[i] = g_w2h1[i]; }
    for (int i = tid; i < 2 * HBUFW; i += RTH) {
        sH0hi[i] = 0u; sH0lo[i] = 0u; sH1hi[i] = 0u; sH1lo[i] = 0u;
    }
    if (tid < MROW) {
        int orow = g_perm[srow0 + tid];
        sPerm[tid] = orow;
        sLen[tid]  = lengths[orow];
        sOff[tid]  = g_off_arr[orow];
    }
    for (int i = tid; i < G4; i += RTH) sB1[i] = bih1[i] + bhh1[i];
    if (tid < HSZ) sWf[tid] = Wfc[tid];
    __syncthreads();

    int Lmax = 0;
    #pragma unroll
    for (int r = 0; r < MROW; r++) Lmax = max(Lmax, sLen[r]);

    const int w = tid >> 5, lane = tid & 31;
    const int g = lane >> 2, tg = lane & 3;
    const int u0 = w * 8 + 2 * tg;
    const bool cv = (u0 < HSZ);

    // Whh0 fragments -> registers (28 x uint2)
    uint2 Wr0[4][7];
    {
        const int lo = (tg * 8 + g) * 2;
        #pragma unroll
        for (int G = 0; G < 4; G++)
            #pragma unroll
            for (int kt = 0; kt < 7; kt++)
                Wr0[G][kt] = *(const uint2*)&g_w2h0[((G * 13 + w) * 7 + kt) * 64 + lo];
    }

    const uint32_t sb = smem_u32(smc);
    const uint32_t lmoff = ((lane & 15) * HROW + (lane >> 4) * 4) * 4;
    const uint32_t h0hiB = sb + OFF_H0HI + lmoff;
    const uint32_t h0loB = sb + OFF_H0LO + lmoff;
    const uint32_t h1hiB = sb + OFF_H1HI + lmoff;
    const uint32_t h1loB = sb + OFF_H1LO + lmoff;

    int rown[2], lenr[2], offr[2];
    #pragma unroll
    for (int ri = 0; ri < 2; ri++) {
        rown[ri] = ri * 8 + g;
        lenr[ri] = sLen[rown[ri]];
        offr[ri] = sOff[rown[ri]];
    }
    float c0[2][2] = {{0.f,0.f},{0.f,0.f}}, h0r[2][2] = {{0.f,0.f},{0.f,0.f}};
    float c1[2][2] = {{0.f,0.f},{0.f,0.f}}, h1r[2][2] = {{0.f,0.f},{0.f,0.f}};

    int p = 0;
    #pragma unroll 1
    for (int t = 0; t < Lmax; t++) {
        // ---- z0(t) prefetch (consumed after MMA-L0) ----
        float2 zn[2][4];
        #pragma unroll
        for (int ri = 0; ri < 2; ri++) {
            const bool lv = cv && (t < lenr[ri]);
            const size_t zb = (size_t)(offr[ri] + t) * G4;
            #pragma unroll
            for (int G = 0; G < 4; G++)
                zn[ri][G] = lv ? *(const float2*)&g_z0pack[zb + G * HSZ + u0]
                               : make_float2(0.f, 0.f);
        }

        // ---- MMA L0: Whh0 (regs) x h0(t-1) ----
        float D[4][4];
        #pragma unroll
        for (int G = 0; G < 4; G++)
            #pragma unroll
            for (int q = 0; q < 4; q++) D[G][q] = 0.f;
        {
            const uint32_t hHi = h0hiB + p * 4352;
            const uint32_t hLo = h0loB + p * 4352;
            #pragma unroll
            for (int kt = 0; kt < 7; kt++) {
                uint32_t ahi[4], alo[4];
                ldsm4(ahi, hHi + kt * 32);
                ldsm4(alo, hLo + kt * 32);
                #pragma unroll
                for (int G = 0; G < 4; G++) {
                    mma_fp16(D[G], ahi, Wr0[G][kt].x, Wr0[G][kt].y);
                    mma_fp16(D[G], alo, Wr0[G][kt].x, Wr0[G][kt].y);
                }
            }
        }
        // ---- act0 -> h0(t) into buffer 1-p ----
        {
            uint32_t* Nh = sH0hi + (1 - p) * HBUFW;
            uint32_t* Nl = sH0lo + (1 - p) * HBUFW;
            #pragma unroll
            for (int ri = 0; ri < 2; ri++) {
                const bool upd = cv && (t < lenr[ri]);
                #pragma unroll
                for (int j = 0; j < 2; j++) {
                    float zi = D[0][ri * 2 + j] + (j ? zn[ri][0].y : zn[ri][0].x);
                    float zf = D[1][ri * 2 + j] + (j ? zn[ri][1].y : zn[ri][1].x);
                    float zg = D[2][ri * 2 + j] + (j ? zn[ri][2].y : zn[ri][2].x);
                    float zo = D[3][ri * 2 + j] + (j ? zn[ri][3].y : zn[ri][3].x);
                    float cn = siga(zf) * c0[ri][j] + siga(zi) * tanha(zg);
                    float hn = siga(zo) * tanha(cn);
                    if (upd) { c0[ri][j] = cn; h0r[ri][j] = hn; }
                }
                uint32_t hw, lw;
                split_h2(h0r[ri][0], h0r[ri][1], hw, lw);
                const int word = rown[ri] * HROW + w * 4 + tg;
                Nh[word] = hw; Nl[word] = lw;
            }
        }
        __syncthreads();

        // ---- MMA L1: Wih1 x h0(t)  +  Whh1 x h1(t-1) ----
        #pragma unroll
        for (int G = 0; G < 4; G++)
            #pragma unroll
            for (int q = 0; q < 4; q++) D[G][q] = 0.f;
        {
            const uint32_t hHi = h0hiB + (1 - p) * 4352;   // h0(t)
            const uint32_t hLo = h0loB + (1 - p) * 4352;
            #pragma unroll
            for (int kt = 0; kt < 7; kt++) {
                uint32_t ahi[4], alo[4];
                ldsm4(ahi, hHi + kt * 32);
                ldsm4(alo, hLo + kt * 32);
                #pragma unroll
                for (int G = 0; G < 4; G++) {
                    const int b2 = (((G * 13 + w) * 7 + kt) * 32 + tg * 8 + g) * 2;
                    uint2 bh = *(const uint2*)&sWi[b2];
                    mma_fp16(D[G], ahi, bh.x, bh.y);
                    mma_fp16(D[G], alo, bh.x, bh.y);
                }
            }
            const uint32_t gHi = h1hiB + p * 4352;         // h1(t-1)
            const uint32_t gLo = h1loB + p * 4352;
            #pragma unroll
            for (int kt = 0; kt < 7; kt++) {
                uint32_t ahi[4], alo[4];
                ldsm4(ahi, gHi + kt * 32);
                ldsm4(alo, gLo + kt * 32);
                #pragma unroll
                for (int G = 0; G < 4; G++) {
                    const int b2 = (((G * 13 + w) * 7 + kt) * 32 + tg * 8 + g) * 2;
                    uint2 bh = *(const uint2*)&sWh[b2];
                    mma_fp16(D[G], ahi, bh.x, bh.y);
                    mma_fp16(D[G], alo, bh.x, bh.y);
                }
            }
        }
        // ---- act1 (+bias1) -> h1(t) into buffer 1-p ----
        {
            uint32_t* Nh = sH1hi + (1 - p) * HBUFW;
            uint32_t* Nl = sH1lo + (1 - p) * HBUFW;
            float bi0 = cv ? sB1[u0]       : 0.f, bi1 = cv ? sB1[u0 + 1]       : 0.f;
            float bf0 = cv ? sB1[100 + u0] : 0.f, bf1 = cv ? sB1[100 + u0 + 1] : 0.f;
            float bg0 = cv ? sB1[200 + u0] : 0.f, bg1 = cv ? sB1[200 + u0 + 1] : 0.f;
            float bo0 = cv ? sB1[300 + u0] : 0.f, bo1 = cv ? sB1[300 + u0 + 1] : 0.f;
            #pragma unroll
            for (int ri = 0; ri < 2; ri++) {
                const bool upd = cv && (t < lenr[ri]);
                #pragma unroll
                for (int j = 0; j < 2; j++) {
                    float zi = D[0][ri * 2 + j] + (j ? bi1 : bi0);
                    float zf = D[1][ri * 2 + j] + (j ? bf1 : bf0);
                    float zg = D[2][ri * 2 + j] + (j ? bg1 : bg0);
                    float zo = D[3][ri * 2 + j] + (j ? bo1 : bo0);
                    float cn = siga(zf) * c1[ri][j] + siga(zi) * tanha(zg);
                    float hn = siga(zo) * tanha(cn);
                    if (upd) { c1[ri][j] = cn; h1r[ri][j] = hn; }
                }
                uint32_t hw, lw;
                split_h2(h1r[ri][0], h1r[ri][1], hw, lw);
                const int word = rown[ri] * HROW + w * 4 + tg;
                Nh[word] = hw; Nl[word] = lw;
            }
        }
        __syncthreads();
        p ^= 1;
    }

    // ---- fc epilogue: out[perm] = h1_final . Wfc + b ----
    #pragma unroll
    for (int ri = 0; ri < 2; ri++) {
        if (cv) {
            sHF[rown[ri] * HSZ + u0]     = h1r[ri][0];
            sHF[rown[ri] * HSZ + u0 + 1] = h1r[ri][1];
        }
    }
    __syncthreads();
    if (tid < MROW) {
        float s = bfc[0];
        #pragma unroll 10
        for (int k = 0; k < HSZ; k++) s += sHF[tid * HSZ + k] * sWf[k];
        out[sPerm[tid]] = s;
    }
}

// ===========================================================================
// Launch   (order chosen so ncu -s 5 -c 1 captures k_fused)
// ===========================================================================
extern "C" void kernel_launch(void* const* d_in, const int* in_sizes, int n_in,
                              void* d_out, int out_size)
{
    const float* x       = (const float*)d_in[0];
    const int*   lengths = (const int*)  d_in[1];
    const float* Wih0    = (const float*)d_in[2];
    const float* Whh0    = (const float*)d_in[3];
    const float* bih0    = (const float*)d_in[4];
    const float* bhh0    = (const float*)d_in[5];
    const float* Wih1    = (const float*)d_in[6];
    const float* Whh1    = (const float*)d_in[7];
    const float* bih1    = (const float*)d_in[8];
    const float* bhh1    = (const float*)d_in[9];
    const float* Wfc     = (const float*)d_in[10];
    const float* bfc     = (const float*)d_in[11];
    float* out = (float*)d_out;

    cudaFuncSetAttribute(k_fused, cudaFuncAttributeMaxDynamicSharedMemorySize, SMR);

    const int gridF = BSZ / MROW;   // 256 CTAs, longest first
    k_scan    <<<1, 512>>>(lengths);                                  // 1
    k_zx0     <<<128, 512>>>(x, lengths, Wih0, bih0, bhh0);           // 2
    k_sortperm<<<1, 512>>>(lengths);                                  // 3
    k_wprep2  <<<dim3((W2N + 255) / 256, 2), 256>>>(Whh0, Whh1);      // 4
    k_wprep1  <<<(W2N + 255) / 256, 256>>>(Wih1);                     // 5
    k_fused   <<<gridF, RTH, SMR>>>(lengths, bih1, bhh1, Wfc, bfc, out); // 6
}

// round 15
// speedup vs baseline: 1.6779x; 1.0172x over previous
#include <cuda_runtime.h>
#include <cuda_fp16.h>
#include <cstdint>
#include <cstddef>

// Problem constants
#define BSZ 4096
#define TSZ 100
#define FSZ 13
#define HSZ 100
#define G4  400

// Fused kernel constants
#define RW    13
#define RTH   (RW*32)
#define W2N   23296         // W fragment words (52 ntiles * 7 kt * 64)
#define HROW  68            // h row stride in words (ldmatrix conflict-free)
#define MROW  16            // batch rows per CTA (sorted by length)
#define HBUFW (MROW*HROW)   // 1088 words per single buffer

// SMEM byte offsets (fused kernel)
#define OFF_WI   0           // Wih1 frags   93184
#define OFF_WH   93184       // Whh1 frags   93184
#define OFF_H0HI 186368      // 2 x 4352
#define OFF_H0LO 195072
#define OFF_H1HI 203776
#define OFF_H1LO 212480
#define OFF_LEN  221184
#define OFF_OFFA 221248
#define OFF_PERM 221312
#define OFF_B1   221376      // 400 floats
#define OFF_WF   222976      // 100 floats
#define SMR      223488

// ---------------------------------------------------------------------------
// Scratch (device globals)
// ---------------------------------------------------------------------------
__device__ float g_z0pack[(size_t)BSZ * TSZ * G4];   // layer-0 z (bias0 + Wx)
__device__ int   g_off_arr[BSZ + 1];
__device__ int   g_perm[BSZ];                        // rows sorted by len desc
__device__ uint32_t g_w2h0[W2N];                     // Whh0 frag layout
__device__ uint32_t g_w2h1[W2N];                     // Whh1 frag layout
__device__ uint32_t g_w2i1[W2N];                     // Wih1 frag layout

// ---------------------------------------------------------------------------
// Helpers
// ---------------------------------------------------------------------------
__device__ __forceinline__ float tanha(float x) {
    float y;
    asm("tanh.approx.f32 %0, %1;" : "=f"(y) : "f"(x));
    return y;
}
__device__ __forceinline__ float siga(float x) {
    return fmaf(0.5f, tanha(0.5f * x), 0.5f);
}
__device__ __forceinline__ void ffma2(unsigned long long &d,
                                      unsigned long long a,
                                      unsigned long long b) {
    asm("fma.rn.f32x2 %0, %1, %2, %0;" : "+l"(d) : "l"(a), "l"(b));
}
__device__ __forceinline__ unsigned long long pk(float lo, float hi) {
    unsigned long long r;
    asm("mov.b64 %0, {%1, %2};" : "=l"(r) : "f"(lo), "f"(hi));
    return r;
}
__device__ __forceinline__ float psum(unsigned long long a) {
    float lo = __uint_as_float((unsigned)(a & 0xffffffffull));
    float hi = __uint_as_float((unsigned)(a >> 32));
    return lo + hi;
}
__device__ __forceinline__ void mma_fp16(float* d, const uint32_t* a,
                                         uint32_t b0, uint32_t b1) {
    asm volatile(
        "mma.sync.aligned.m16n8k16.row.col.f32.f16.f16.f32 "
        "{%0,%1,%2,%3}, {%4,%5,%6,%7}, {%8,%9}, {%0,%1,%2,%3};"
        : "+f"(d[0]), "+f"(d[1]), "+f"(d[2]), "+f"(d[3])
        : "r"(a[0]), "r"(a[1]), "r"(a[2]), "r"(a[3]), "r"(b0), "r"(b1));
}
__device__ __forceinline__ void ldsm4(uint32_t* r, uint32_t addr) {
    asm volatile("ldmatrix.sync.aligned.m8n8.x4.shared.b16 {%0,%1,%2,%3}, [%4];"
        : "=r"(r[0]), "=r"(r[1]), "=r"(r[2]), "=r"(r[3]) : "r"(addr));
}
__device__ __forceinline__ uint32_t smem_u32(const void* p) {
    uint32_t a;
    asm("{ .reg .u64 t; cvta.to.shared.u64 t, %1; cvt.u32.u64 %0, t; }"
        : "=r"(a) : "l"(p));
    return a;
}
__device__ __forceinline__ void split_h2(float f0, float f1,
                                         uint32_t &hw, uint32_t &lw) {
    __half2 h2 = __float22half2_rn(make_float2(f0, f1));
    hw = *(uint32_t*)&h2;
    float2 back = __half22float2(h2);
    __half2 l2 = __float22half2_rn(make_float2(f0 - back.x, f1 - back.y));
    lw = *(uint32_t*)&l2;
}

// ===========================================================================
// Kernel S: exclusive prefix scan of lengths (1 CTA)
// ===========================================================================
__global__ void __launch_bounds__(512, 1) k_scan(const int* __restrict__ lengths)
{
    __shared__ int s[512];
    const int tid = threadIdx.x;
    const int base = tid * 8;
    int v[8]; int loc = 0;
    #pragma unroll
    for (int i = 0; i < 8; i++) { v[i] = lengths[base + i]; loc += v[i]; }
    s[tid] = loc;
    __syncthreads();
    for (int d = 1; d < 512; d <<= 1) {
        int t = (tid >= d) ? s[tid - d] : 0;
        __syncthreads();
        s[tid] += t;
        __syncthreads();
    }
    int run = s[tid] - loc;
    #pragma unroll
    for (int i = 0; i < 8; i++) { g_off_arr[base + i] = run; run += v[i]; }
    if (tid == 511) g_off_arr[BSZ] = s[511];
}

// ===========================================================================
// Kernel P: counting sort by length (descending) -> g_perm
// ===========================================================================
__global__ void __launch_bounds__(512, 1) k_sortperm(const int* __restrict__ lengths)
{
    __shared__ int bins[101];
    const int tid = threadIdx.x;
    if (tid < 101) bins[tid] = 0;
    __syncthreads();
    for (int i = tid; i < BSZ; i += 512)
        atomicAdd(&bins[100 - lengths[i]], 1);
    __syncthreads();
    if (tid == 0) {
        int run = 0;
        for (int k = 0; k <= 100; k++) { int c = bins[k]; bins[k] = run; run += c; }
    }
    __syncthreads();
    for (int i = tid; i < BSZ; i += 512) {
        int pos = atomicAdd(&bins[100 - lengths[i]], 1);
        g_perm[pos] = i;
    }
}

// ===========================================================================
// Kernel W: W[400][100] -> fp16 pair-packed fragment layout
// ===========================================================================
__device__ __forceinline__ void wprep_one(const float* __restrict__ W,
                                          uint32_t* __restrict__ dh, int j)
{
    int sel = j & 1;
    int pp  = (j >> 1) & 31;
    int tg  = pp >> 3, g = pp & 7;
    int grp = j >> 6;
    int kt  = grp % 7, n = grp / 7;
    int row = n * 8 + g;
    int gate = row / 104, u = row % 104;
    int k    = kt * 16 + 2 * tg + 8 * sel;
    float f0 = (u < HSZ && k     < HSZ) ? W[(gate * HSZ + u) * HSZ + k]     : 0.f;
    float f1 = (u < HSZ && k + 1 < HSZ) ? W[(gate * HSZ + u) * HSZ + k + 1] : 0.f;
    __half2 h2 = __float22half2_rn(make_float2(f0, f1));
    dh[j] = *(uint32_t*)&h2;
}

__global__ void __launch_bounds__(256, 1)
k_wprep3(const float* __restrict__ W0, const float* __restrict__ W1,
         const float* __restrict__ Wi)
{
    int j = blockIdx.x * 256 + threadIdx.x;
    if (j >= W2N) return;
    if (blockIdx.y == 0)      wprep_one(W0, g_w2h0, j);
    else if (blockIdx.y == 1) wprep_one(W1, g_w2h1, j);
    else                      wprep_one(Wi, g_w2i1, j);
}

// ===========================================================================
// Kernel Z0: g_z0pack = bias0 + x @ Wih0^T (packed rows, fp32)
// ===========================================================================
__global__ void __launch_bounds__(512, 1)
k_zx0(const float* __restrict__ x, const int* __restrict__ lengths,
      const float* __restrict__ Wih0,
      const float* __restrict__ bih0, const float* __restrict__ bhh0)
{
    __shared__ float sX[1400];
    __shared__ int sLen[32], sOff[32];
    const int tid = threadIdx.x;
    const int grow0 = blockIdx.x * 32;
    if (tid < 32) {
        sLen[tid] = lengths[grow0 + tid];
        sOff[tid] = g_off_arr[grow0 + tid];
    }
    const int u = tid;
    const bool act = (u < G4);
    unsigned long long wp[7];
    float b = 0.f;
    if (act) {
        float wr[14];
        #pragma unroll
        for (int k = 0; k < FSZ; k++) wr[k] = Wih0[u * FSZ + k];
        wr[13] = 0.f;
        #pragma unroll
        for (int i = 0; i < 7; i++) wp[i] = pk(wr[2*i], wr[2*i+1]);
        b = bih0[u] + bhh0[u];
    }
    __syncthreads();

    for (int r = 0; r < 32; r++) {
        const int len = sLen[r], off = sOff[r];
        __syncthreads();
        const float* xs = x + (size_t)(grow0 + r) * (TSZ * FSZ);
        for (int i = tid; i < 1400; i += 512) {
            int t = i / 14, k = i % 14;
            sX[i] = (k < FSZ) ? xs[t * FSZ + k] : 0.f;
        }
        __syncthreads();
        if (act) {
            for (int t = 0; t < len; t++) {
                unsigned long long acc = pk(b, 0.f);
                #pragma unroll
                for (int kp = 0; kp < 7; kp++)
                    ffma2(acc, wp[kp], *(const unsigned long long*)&sX[t*14 + 2*kp]);
                g_z0pack[(size_t)(off + t) * G4 + u] = psum(acc);
            }
        }
    }
}

// ===========================================================================
// Kernel F: FUSED 2-layer LSTM, one-step software pipeline
//   iteration i computes h0(i) and h1(i-1):
//     ONE MMA block:  D0 = Whh0*h0(i-1) ; Dz = Wih1*h0(i-1) + Whh1*h1(i-2)
//     ONE act block:  h0(i) = act0(D0 + z0(i)) ; h1(i-1) = act1(Dz + b1)
//     ONE barrier
// ===========================================================================
__global__ void __launch_bounds__(RTH, 1)
k_fused(const int* __restrict__ lengths,
        const float* __restrict__ bih1, const float* __restrict__ bhh1,
        const float* __restrict__ Wfc, const float* __restrict__ bfc,
        float* __restrict__ out)
{
    extern __shared__ char smc[];
    uint32_t* sWi   = (uint32_t*)(smc + OFF_WI);
    uint32_t* sWh   = (uint32_t*)(smc + OFF_WH);
    uint32_t* sH0hi = (uint32_t*)(smc + OFF_H0HI);
    uint32_t* sH0lo = (uint32_t*)(smc + OFF_H0LO);
    uint32_t* sH1hi = (uint32_t*)(smc + OFF_H1HI);
    uint32_t* sH1lo = (uint32_t*)(smc + OFF_H1LO);
    int*   sLen  = (int*)(smc + OFF_LEN);
    int*   sOff  = (int*)(smc + OFF_OFFA);
    int*   sPerm = (int*)(smc + OFF_PERM);
    float* sB1   = (float*)(smc + OFF_B1);
    float* sWf   = (float*)(smc + OFF_WF);
    float* sHF   = (float*)smc;     // fc staging, reused after loop

    const int tid = threadIdx.x;
    const int srow0 = blockIdx.x * MROW;

    for (int i = tid; i < W2N; i += RTH) { sWi[i] = g_w2i1[i]; sWh[i] = g_w2h1[i]; }
    for (int i = tid; i < 2 * HBUFW; i += RTH) {
        sH0hi[i] = 0u; sH0lo[i] = 0u; sH1hi[i] = 0u; sH1lo[i] = 0u;
    }
    if (tid < MROW) {
        int orow = g_perm[srow0 + tid];
        sPerm[tid] = orow;
        sLen[tid]  = lengths[orow];
        sOff[tid]  = g_off_arr[orow];
    }
    for (int i = tid; i < G4; i += RTH) sB1[i] = bih1[i] + bhh1[i];
    if (tid < HSZ) sWf[tid] = Wfc[tid];
    __syncthreads();

    int Lmax = 0;
    #pragma unroll
    for (int r = 0; r < MROW; r++) Lmax = max(Lmax, sLen[r]);

    const int w = tid >> 5, lane = tid & 31;
    const int g = lane >> 2, tg = lane & 3;
    const int u0 = w * 8 + 2 * tg;
    const bool cv = (u0 < HSZ);

    // Whh0 fragments -> registers (28 x uint2)
    uint2 Wr0[4][7];
    {
        const int lo = (tg * 8 + g) * 2;
        #pragma unroll
        for (int G = 0; G < 4; G++)
            #pragma unroll
            for (int kt = 0; kt < 7; kt++)
                Wr0[G][kt] = *(const uint2*)&g_w2h0[((G * 13 + w) * 7 + kt) * 64 + lo];
    }

    const uint32_t sb = smem_u32(smc);
    const uint32_t lmoff = ((lane & 15) * HROW + (lane >> 4) * 4) * 4;
    const uint32_t h0hiB = sb + OFF_H0HI + lmoff;
    const uint32_t h0loB = sb + OFF_H0LO + lmoff;
    const uint32_t h1hiB = sb + OFF_H1HI + lmoff;
    const uint32_t h1loB = sb + OFF_H1LO + lmoff;

    int rown[2], lenr[2], offr[2];
    #pragma unroll
    for (int ri = 0; ri < 2; ri++) {
        rown[ri] = ri * 8 + g;
        lenr[ri] = sLen[rown[ri]];
        offr[ri] = sOff[rown[ri]];
    }
    float c0[2][2] = {{0.f,0.f},{0.f,0.f}}, h0r[2][2] = {{0.f,0.f},{0.f,0.f}};
    float c1[2][2] = {{0.f,0.f},{0.f,0.f}}, h1r[2][2] = {{0.f,0.f},{0.f,0.f}};

    const float bi0 = cv ? sB1[u0]       : 0.f, bi1 = cv ? sB1[u0 + 1]       : 0.f;
    const float bf0 = cv ? sB1[100 + u0] : 0.f, bf1 = cv ? sB1[100 + u0 + 1] : 0.f;
    const float bg0 = cv ? sB1[200 + u0] : 0.f, bg1 = cv ? sB1[200 + u0 + 1] : 0.f;
    const float bo0 = cv ? sB1[300 + u0] : 0.f, bo1 = cv ? sB1[300 + u0 + 1] : 0.f;

    int p = 0;
    #pragma unroll 1
    for (int i = 0; i <= Lmax; i++) {
        // ---- z0(i) prefetch (for h0(i) act; consumed after MMA block) ----
        float2 zn[2][4];
        #pragma unroll
        for (int ri = 0; ri < 2; ri++) {
            const bool lv = cv && (i < lenr[ri]);
            const size_t zb = (size_t)(offr[ri] + i) * G4;
            #pragma unroll
            for (int G = 0; G < 4; G++)
                zn[ri][G] = lv ? *(const float2*)&g_z0pack[zb + G * HSZ + u0]
                               : make_float2(0.f, 0.f);
        }

        // ---- single MMA block: D0 (layer0) and Dz (layer1) ----
        float D0[4][4], Dz[4][4];
        #pragma unroll
        for (int G = 0; G < 4; G++)
            #pragma unroll
            for (int q = 0; q < 4; q++) { D0[G][q] = 0.f; Dz[G][q] = 0.f; }
        {
            const uint32_t hHi = h0hiB + p * 4352;   // h0(i-1)
            const uint32_t hLo = h0loB + p * 4352;
            #pragma unroll
            for (int kt = 0; kt < 7; kt++) {
                uint32_t ahi[4], alo[4];
                ldsm4(ahi, hHi + kt * 32);
                ldsm4(alo, hLo + kt * 32);
                #pragma unroll
                for (int G = 0; G < 4; G++) {
                    // layer0: Whh0 (registers)
                    mma_fp16(D0[G], ahi, Wr0[G][kt].x, Wr0[G][kt].y);
                    mma_fp16(D0[G], alo, Wr0[G][kt].x, Wr0[G][kt].y);
                    // layer1 input part: Wih1 x h0(i-1)
                    const int b2 = (((G * 13 + w) * 7 + kt) * 32 + tg * 8 + g) * 2;
                    uint2 bh = *(const uint2*)&sWi[b2];
                    mma_fp16(Dz[G], ahi, bh.x, bh.y);
                    mma_fp16(Dz[G], alo, bh.x, bh.y);
                }
            }
            const uint32_t gHi = h1hiB + p * 4352;   // h1(i-2)
            const uint32_t gLo = h1loB + p * 4352;
            #pragma unroll
            for (int kt = 0; kt < 7; kt++) {
                uint32_t ahi[4], alo[4];
                ldsm4(ahi, gHi + kt * 32);
                ldsm4(alo, gLo + kt * 32);
                #pragma unroll
                for (int G = 0; G < 4; G++) {
                    const int b2 = (((G * 13 + w) * 7 + kt) * 32 + tg * 8 + g) * 2;
                    uint2 bh = *(const uint2*)&sWh[b2];
                    mma_fp16(Dz[G], ahi, bh.x, bh.y);
                    mma_fp16(Dz[G], alo, bh.x, bh.y);
                }
            }
        }

        // ---- combined act block ----
        // h0(i)   (skip at i == Lmax)
        if (i < Lmax) {
            uint32_t* Nh = sH0hi + (1 - p) * HBUFW;
            uint32_t* Nl = sH0lo + (1 - p) * HBUFW;
            #pragma unroll
            for (int ri = 0; ri < 2; ri++) {
                const bool upd = cv && (i < lenr[ri]);
                #pragma unroll
                for (int j = 0; j < 2; j++) {
                    float zi = D0[0][ri * 2 + j] + (j ? zn[ri][0].y : zn[ri][0].x);
                    float zf = D0[1][ri * 2 + j] + (j ? zn[ri][1].y : zn[ri][1].x);
                    float zg = D0[2][ri * 2 + j] + (j ? zn[ri][2].y : zn[ri][2].x);
                    float zo = D0[3][ri * 2 + j] + (j ? zn[ri][3].y : zn[ri][3].x);
                    float cn = siga(zf) * c0[ri][j] + siga(zi) * tanha(zg);
                    float hn = siga(zo) * tanha(cn);
                    if (upd) { c0[ri][j] = cn; h0r[ri][j] = hn; }
                }
                uint32_t hw, lw;
                split_h2(h0r[ri][0], h0r[ri][1], hw, lw);
                const int word = rown[ri] * HROW + w * 4 + tg;
                Nh[word] = hw; Nl[word] = lw;
            }
        }
        // h1(i-1) (skip at i == 0)
        if (i >= 1) {
            uint32_t* Nh = sH1hi + (1 - p) * HBUFW;
            uint32_t* Nl = sH1lo + (1 - p) * HBUFW;
            const int tb = i - 1;
            #pragma unroll
            for (int ri = 0; ri < 2; ri++) {
                const bool upd = cv && (tb < lenr[ri]);
                #pragma unroll
                for (int j = 0; j < 2; j++) {
                    float zi = Dz[0][ri * 2 + j] + (j ? bi1 : bi0);
                    float zf = Dz[1][ri * 2 + j] + (j ? bf1 : bf0);
                    float zg = Dz[2][ri * 2 + j] + (j ? bg1 : bg0);
                    float zo = Dz[3][ri * 2 + j] + (j ? bo1 : bo0);
                    float cn = siga(zf) * c1[ri][j] + siga(zi) * tanha(zg);
                    float hn = siga(zo) * tanha(cn);
                    if (upd) { c1[ri][j] = cn; h1r[ri][j] = hn; }
                }
                uint32_t hw, lw;
                split_h2(h1r[ri][0], h1r[ri][1], hw, lw);
                const int word = rown[ri] * HROW + w * 4 + tg;
                Nh[word] = hw; Nl[word] = lw;
            }
        }
        __syncthreads();
        p ^= 1;
    }

    // ---- fc epilogue: out[perm] = h1_final . Wfc + b ----
    #pragma unroll
    for (int ri = 0; ri < 2; ri++) {
        if (cv) {
            sHF[rown[ri] * HSZ + u0]     = h1r[ri][0];
            sHF[rown[ri] * HSZ + u0 + 1] = h1r[ri][1];
        }
    }
    __syncthreads();
    if (tid < MROW) {
        float s = bfc[0];
        #pragma unroll 10
        for (int k = 0; k < HSZ; k++) s += sHF[tid * HSZ + k] * sWf[k];
        out[sPerm[tid]] = s;
    }
}

// ===========================================================================
// Launch
// ===========================================================================
extern "C" void kernel_launch(void* const* d_in, const int* in_sizes, int n_in,
                              void* d_out, int out_size)
{
    const float* x       = (const float*)d_in[0];
    const int*   lengths = (const int*)  d_in[1];
    const float* Wih0    = (const float*)d_in[2];
    const float* Whh0    = (const float*)d_in[3];
    const float* bih0    = (const float*)d_in[4];
    const float* bhh0    = (const float*)d_in[5];
    const float* Wih1    = (const float*)d_in[6];
    const float* Whh1    = (const float*)d_in[7];
    const float* bih1    = (const float*)d_in[8];
    const float* bhh1    = (const float*)d_in[9];
    const float* Wfc     = (const float*)d_in[10];
    const float* bfc     = (const float*)d_in[11];
    float* out = (float*)d_out;

    cudaFuncSetAttribute(k_fused, cudaFuncAttributeMaxDynamicSharedMemorySize, SMR);

    const int gridF = BSZ / MROW;   // 256 CTAs, longest first
    k_scan    <<<1, 512>>>(lengths);
    k_zx0     <<<128, 512>>>(x, lengths, Wih0, bih0, bhh0);
    k_sortperm<<<1, 512>>>(lengths);
    k_wprep3  <<<dim3((W2N + 255) / 256, 3), 256>>>(Whh0, Whh1, Wih1);
    k_fused   <<<gridF, RTH, SMR>>>(lengths, bih1, bhh1, Wfc, bfc, out);
}

// round 16
// speedup vs baseline: 1.7587x; 1.0481x over previous
#include <cuda_runtime.h>
#include <cuda_fp16.h>
#include <cstdint>
#include <cstddef>

// Problem constants
#define BSZ 4096
#define TSZ 100
#define FSZ 13
#define HSZ 100
#define G4  400

// Fused kernel constants
#define RW    13
#define RTH   (RW*32)
#define W2N   23296         // W fragment words (52 ntiles * 7 kt * 64)
#define HROW  68            // h row stride in words (ldmatrix conflict-free)
#define MROW  16            // batch rows per CTA (sorted by length)
#define HBUFW (MROW*HROW)   // 1088 words per single buffer

// SMEM byte offsets (fused kernel)
#define OFF_WI   0           // Wih1 frags   93184
#define OFF_WH   93184       // Whh1 frags   93184
#define OFF_H0HI 186368      // 2 x 4352
#define OFF_H0LO 195072      // 2 x 4352
#define OFF_H1HI 203776      // 2 x 4352 (hi only; lo term dropped in L1)
#define OFF_LEN  212480
#define OFF_OFFA 212544
#define OFF_PERM 212608
#define OFF_B1   212672      // 400 floats
#define OFF_WF   214272      // 100 floats
#define SMR      214784

// ---------------------------------------------------------------------------
// Scratch (device globals)
// ---------------------------------------------------------------------------
__device__ float g_z0pack[(size_t)BSZ * TSZ * G4];   // layer-0 z (bias0 + Wx)
__device__ int   g_off_arr[BSZ + 1];
__device__ int   g_perm[BSZ];                        // rows sorted by len desc
__device__ uint32_t g_w2h0[W2N];                     // Whh0 frag layout
__device__ uint32_t g_w2h1[W2N];                     // Whh1 frag layout
__device__ uint32_t g_w2i1[W2N];                     // Wih1 frag layout

// ---------------------------------------------------------------------------
// Helpers
// ---------------------------------------------------------------------------
__device__ __forceinline__ float tanha(float x) {
    float y;
    asm("tanh.approx.f32 %0, %1;" : "=f"(y) : "f"(x));
    return y;
}
__device__ __forceinline__ float siga(float x) {
    return fmaf(0.5f, tanha(0.5f * x), 0.5f);
}
__device__ __forceinline__ void ffma2(unsigned long long &d,
                                      unsigned long long a,
                                      unsigned long long b) {
    asm("fma.rn.f32x2 %0, %1, %2, %0;" : "+l"(d) : "l"(a), "l"(b));
}
__device__ __forceinline__ unsigned long long pk(float lo, float hi) {
    unsigned long long r;
    asm("mov.b64 %0, {%1, %2};" : "=l"(r) : "f"(lo), "f"(hi));
    return r;
}
__device__ __forceinline__ float psum(unsigned long long a) {
    float lo = __uint_as_float((unsigned)(a & 0xffffffffull));
    float hi = __uint_as_float((unsigned)(a >> 32));
    return lo + hi;
}
__device__ __forceinline__ void mma_fp16(float* d, const uint32_t* a,
                                         uint32_t b0, uint32_t b1) {
    asm volatile(
        "mma.sync.aligned.m16n8k16.row.col.f32.f16.f16.f32 "
        "{%0,%1,%2,%3}, {%4,%5,%6,%7}, {%8,%9}, {%0,%1,%2,%3};"
        : "+f"(d[0]), "+f"(d[1]), "+f"(d[2]), "+f"(d[3])
        : "r"(a[0]), "r"(a[1]), "r"(a[2]), "r"(a[3]), "r"(b0), "r"(b1));
}
__device__ __forceinline__ void ldsm4(uint32_t* r, uint32_t addr) {
    asm volatile("ldmatrix.sync.aligned.m8n8.x4.shared.b16 {%0,%1,%2,%3}, [%4];"
        : "=r"(r[0]), "=r"(r[1]), "=r"(r[2]), "=r"(r[3]) : "r"(addr));
}
__device__ __forceinline__ uint32_t smem_u32(const void* p) {
    uint32_t a;
    asm("{ .reg .u64 t; cvta.to.shared.u64 t, %1; cvt.u32.u64 %0, t; }"
        : "=r"(a) : "l"(p));
    return a;
}
__device__ __forceinline__ void split_h2(float f0, float f1,
                                         uint32_t &hw, uint32_t &lw) {
    __half2 h2 = __float22half2_rn(make_float2(f0, f1));
    hw = *(uint32_t*)&h2;
    float2 back = __half22float2(h2);
    __half2 l2 = __float22half2_rn(make_float2(f0 - back.x, f1 - back.y));
    lw = *(uint32_t*)&l2;
}
__device__ __forceinline__ uint32_t pack_h2(float f0, float f1) {
    __half2 h2 = __float22half2_rn(make_float2(f0, f1));
    return *(uint32_t*)&h2;
}

// ===========================================================================
// Kernel S: exclusive prefix scan of lengths (1 CTA)
// ===========================================================================
__global__ void __launch_bounds__(512, 1) k_scan(const int* __restrict__ lengths)
{
    __shared__ int s[512];
    const int tid = threadIdx.x;
    const int base = tid * 8;
    int v[8]; int loc = 0;
    #pragma unroll
    for (int i = 0; i < 8; i++) { v[i] = lengths[base + i]; loc += v[i]; }
    s[tid] = loc;
    __syncthreads();
    for (int d = 1; d < 512; d <<= 1) {
        int t = (tid >= d) ? s[tid - d] : 0;
        __syncthreads();
        s[tid] += t;
        __syncthreads();
    }
    int run = s[tid] - loc;
    #pragma unroll
    for (int i = 0; i < 8; i++) { g_off_arr[base + i] = run; run += v[i]; }
    if (tid == 511) g_off_arr[BSZ] = s[511];
}

// ===========================================================================
// Kernel P: counting sort by length (descending) -> g_perm
// ===========================================================================
__global__ void __launch_bounds__(512, 1) k_sortperm(const int* __restrict__ lengths)
{
    __shared__ int bins[101];
    const int tid = threadIdx.x;
    if (tid < 101) bins[tid] = 0;
    __syncthreads();
    for (int i = tid; i < BSZ; i += 512)
        atomicAdd(&bins[100 - lengths[i]], 1);
    __syncthreads();
    if (tid == 0) {
        int run = 0;
        for (int k = 0; k <= 100; k++) { int c = bins[k]; bins[k] = run; run += c; }
    }
    __syncthreads();
    for (int i = tid; i < BSZ; i += 512) {
        int pos = atomicAdd(&bins[100 - lengths[i]], 1);
        g_perm[pos] = i;
    }
}

// ===========================================================================
// Kernel W: W[400][100] -> fp16 pair-packed fragment layout
// ===========================================================================
__device__ __forceinline__ void wprep_one(const float* __restrict__ W,
                                          uint32_t* __restrict__ dh, int j)
{
    int sel = j & 1;
    int pp  = (j >> 1) & 31;
    int tg  = pp >> 3, g = pp & 7;
    int grp = j >> 6;
    int kt  = grp % 7, n = grp / 7;
    int row = n * 8 + g;
    int gate = row / 104, u = row % 104;
    int k    = kt * 16 + 2 * tg + 8 * sel;
    float f0 = (u < HSZ && k     < HSZ) ? W[(gate * HSZ + u) * HSZ + k]     : 0.f;
    float f1 = (u < HSZ && k + 1 < HSZ) ? W[(gate * HSZ + u) * HSZ + k + 1] : 0.f;
    __half2 h2 = __float22half2_rn(make_float2(f0, f1));
    dh[j] = *(uint32_t*)&h2;
}

__global__ void __launch_bounds__(256, 1)
k_wprep3(const float* __restrict__ W0, const float* __restrict__ W1,
         const float* __restrict__ Wi)
{
    int j = blockIdx.x * 256 + threadIdx.x;
    if (j >= W2N) return;
    if (blockIdx.y == 0)      wprep_one(W0, g_w2h0, j);
    else if (blockIdx.y == 1) wprep_one(W1, g_w2h1, j);
    else                      wprep_one(Wi, g_w2i1, j);
}

// ===========================================================================
// Kernel Z0: g_z0pack = bias0 + x @ Wih0^T (packed rows, fp32)
// ===========================================================================
__global__ void __launch_bounds__(512, 1)
k_zx0(const float* __restrict__ x, const int* __restrict__ lengths,
      const float* __restrict__ Wih0,
      const float* __restrict__ bih0, const float* __restrict__ bhh0)
{
    __shared__ float sX[1400];
    __shared__ int sLen[32], sOff[32];
    const int tid = threadIdx.x;
    const int grow0 = blockIdx.x * 32;
    if (tid < 32) {
        sLen[tid] = lengths[grow0 + tid];
        sOff[tid] = g_off_arr[grow0 + tid];
    }
    const int u = tid;
    const bool act = (u < G4);
    unsigned long long wp[7];
    float b = 0.f;
    if (act) {
        float wr[14];
        #pragma unroll
        for (int k = 0; k < FSZ; k++) wr[k] = Wih0[u * FSZ + k];
        wr[13] = 0.f;
        #pragma unroll
        for (int i = 0; i < 7; i++) wp[i] = pk(wr[2*i], wr[2*i+1]);
        b = bih0[u] + bhh0[u];
    }
    __syncthreads();

    for (int r = 0; r < 32; r++) {
        const int len = sLen[r], off = sOff[r];
        __syncthreads();
        const float* xs = x + (size_t)(grow0 + r) * (TSZ * FSZ);
        for (int i = tid; i < 1400; i += 512) {
            int t = i / 14, k = i % 14;
            sX[i] = (k < FSZ) ? xs[t * FSZ + k] : 0.f;
        }
        __syncthreads();
        if (act) {
            for (int t = 0; t < len; t++) {
                unsigned long long acc = pk(b, 0.f);
                #pragma unroll
                for (int kp = 0; kp < 7; kp++)
                    ffma2(acc, wp[kp], *(const unsigned long long*)&sX[t*14 + 2*kp]);
                g_z0pack[(size_t)(off + t) * G4 + u] = psum(acc);
            }
        }
    }
}

// ===========================================================================
// Kernel F: FUSED 2-layer LSTM, one-step pipeline, reduced L1 precision
//   iteration i computes h0(i) and h1(i-1):
//     MMA block: D0 = Whh0*(h0hi+h0lo)      [full split, recurrence-critical]
//                Dz = Wih1*h0hi + Whh1*h1hi [hi-only, -56 MMAs/step]
//     act block: h0(i), h1(i-1);  ONE barrier
// ===========================================================================
__global__ void __launch_bounds__(RTH, 1)
k_fused(const int* __restrict__ lengths,
        const float* __restrict__ bih1, const float* __restrict__ bhh1,
        const float* __restrict__ Wfc, const float* __restrict__ bfc,
        float* __restrict__ out)
{
    extern __shared__ char smc[];
    uint32_t* sWi   = (uint32_t*)(smc + OFF_WI);
    uint32_t* sWh   = (uint32_t*)(smc + OFF_WH);
    uint32_t* sH0hi = (uint32_t*)(smc + OFF_H0HI);
    uint32_t* sH0lo = (uint32_t*)(smc + OFF_H0LO);
    uint32_t* sH1hi = (uint32_t*)(smc + OFF_H1HI);
    int*   sLen  = (int*)(smc + OFF_LEN);
    int*   sOff  = (int*)(smc + OFF_OFFA);
    int*   sPerm = (int*)(smc + OFF_PERM);
    float* sB1   = (float*)(smc + OFF_B1);
    float* sWf   = (float*)(smc + OFF_WF);
    float* sHF   = (float*)smc;     // fc staging, reused after loop

    const int tid = threadIdx.x;
    const int srow0 = blockIdx.x * MROW;

    for (int i = tid; i < W2N; i += RTH) { sWi[i] = g_w2i1[i]; sWh[i] = g_w2h1[i]; }
    for (int i = tid; i < 2 * HBUFW; i += RTH) {
        sH0hi[i] = 0u; sH0lo[i] = 0u; sH1hi[i] = 0u;
    }
    if (tid < MROW) {
        int orow = g_perm[srow0 + tid];
        sPerm[tid] = orow;
        sLen[tid]  = lengths[orow];
        sOff[tid]  = g_off_arr[orow];
    }
    for (int i = tid; i < G4; i += RTH) sB1[i] = bih1[i] + bhh1[i];
    if (tid < HSZ) sWf[tid] = Wfc[tid];
    __syncthreads();

    int Lmax = 0;
    #pragma unroll
    for (int r = 0; r < MROW; r++) Lmax = max(Lmax, sLen[r]);

    const int w = tid >> 5, lane = tid & 31;
    const int g = lane >> 2, tg = lane & 3;
    const int u0 = w * 8 + 2 * tg;
    const bool cv = (u0 < HSZ);

    // Whh0 fragments -> registers (28 x uint2)
    uint2 Wr0[4][7];
    {
        const int lo = (tg * 8 + g) * 2;
        #pragma unroll
        for (int G = 0; G < 4; G++)
            #pragma unroll
            for (int kt = 0; kt < 7; kt++)
                Wr0[G][kt] = *(const uint2*)&g_w2h0[((G * 13 + w) * 7 + kt) * 64 + lo];
    }

    const uint32_t sb = smem_u32(smc);
    const uint32_t lmoff = ((lane & 15) * HROW + (lane >> 4) * 4) * 4;
    const uint32_t h0hiB = sb + OFF_H0HI + lmoff;
    const uint32_t h0loB = sb + OFF_H0LO + lmoff;
    const uint32_t h1hiB = sb + OFF_H1HI + lmoff;

    int rown[2], lenr[2], offr[2];
    #pragma unroll
    for (int ri = 0; ri < 2; ri++) {
        rown[ri] = ri * 8 + g;
        lenr[ri] = sLen[rown[ri]];
        offr[ri] = sOff[rown[ri]];
    }
    float c0[2][2] = {{0.f,0.f},{0.f,0.f}}, h0r[2][2] = {{0.f,0.f},{0.f,0.f}};
    float c1[2][2] = {{0.f,0.f},{0.f,0.f}}, h1r[2][2] = {{0.f,0.f},{0.f,0.f}};

    const float bi0 = cv ? sB1[u0]       : 0.f, bi1 = cv ? sB1[u0 + 1]       : 0.f;
    const float bf0 = cv ? sB1[100 + u0] : 0.f, bf1 = cv ? sB1[100 + u0 + 1] : 0.f;
    const float bg0 = cv ? sB1[200 + u0] : 0.f, bg1 = cv ? sB1[200 + u0 + 1] : 0.f;
    const float bo0 = cv ? sB1[300 + u0] : 0.f, bo1 = cv ? sB1[300 + u0 + 1] : 0.f;

    int p = 0;
    #pragma unroll 1
    for (int i = 0; i <= Lmax; i++) {
        // ---- z0(i) prefetch (consumed after MMA block) ----
        float2 zn[2][4];
        #pragma unroll
        for (int ri = 0; ri < 2; ri++) {
            const bool lv = cv && (i < lenr[ri]);
            const size_t zb = (size_t)(offr[ri] + i) * G4;
            #pragma unroll
            for (int G = 0; G < 4; G++)
                zn[ri][G] = lv ? *(const float2*)&g_z0pack[zb + G * HSZ + u0]
                               : make_float2(0.f, 0.f);
        }

        // ---- single MMA block ----
        float D0[4][4], Dz[4][4];
        #pragma unroll
        for (int G = 0; G < 4; G++)
            #pragma unroll
            for (int q = 0; q < 4; q++) { D0[G][q] = 0.f; Dz[G][q] = 0.f; }
        {
            const uint32_t hHi = h0hiB + p * 4352;   // h0(i-1)
            const uint32_t hLo = h0loB + p * 4352;
            #pragma unroll
            for (int kt = 0; kt < 7; kt++) {
                uint32_t ahi[4], alo[4];
                ldsm4(ahi, hHi + kt * 32);
                ldsm4(alo, hLo + kt * 32);
                #pragma unroll
                for (int G = 0; G < 4; G++) {
                    // layer0: full hi/lo split (registers)
                    mma_fp16(D0[G], ahi, Wr0[G][kt].x, Wr0[G][kt].y);
                    mma_fp16(D0[G], alo, Wr0[G][kt].x, Wr0[G][kt].y);
                    // layer1 input part: Wih1 x h0_hi only
                    const int b2 = (((G * 13 + w) * 7 + kt) * 32 + tg * 8 + g) * 2;
                    uint2 bh = *(const uint2*)&sWi[b2];
                    mma_fp16(Dz[G], ahi, bh.x, bh.y);
                }
            }
            const uint32_t gHi = h1hiB + p * 4352;   // h1(i-2), hi only
            #pragma unroll
            for (int kt = 0; kt < 7; kt++) {
                uint32_t ahi[4];
                ldsm4(ahi, gHi + kt * 32);
                #pragma unroll
                for (int G = 0; G < 4; G++) {
                    const int b2 = (((G * 13 + w) * 7 + kt) * 32 + tg * 8 + g) * 2;
                    uint2 bh = *(const uint2*)&sWh[b2];
                    mma_fp16(Dz[G], ahi, bh.x, bh.y);
                }
            }
        }

        // ---- combined act block ----
        if (i < Lmax) {          // h0(i)
            uint32_t* Nh = sH0hi + (1 - p) * HBUFW;
            uint32_t* Nl = sH0lo + (1 - p) * HBUFW;
            #pragma unroll
            for (int ri = 0; ri < 2; ri++) {
                const bool upd = cv && (i < lenr[ri]);
                #pragma unroll
                for (int j = 0; j < 2; j++) {
                    float zi = D0[0][ri * 2 + j] + (j ? zn[ri][0].y : zn[ri][0].x);
                    float zf = D0[1][ri * 2 + j] + (j ? zn[ri][1].y : zn[ri][1].x);
                    float zg = D0[2][ri * 2 + j] + (j ? zn[ri][2].y : zn[ri][2].x);
                    float zo = D0[3][ri * 2 + j] + (j ? zn[ri][3].y : zn[ri][3].x);
                    float cn = siga(zf) * c0[ri][j] + siga(zi) * tanha(zg);
                    float hn = siga(zo) * tanha(cn);
                    if (upd) { c0[ri][j] = cn; h0r[ri][j] = hn; }
                }
                uint32_t hw, lw;
                split_h2(h0r[ri][0], h0r[ri][1], hw, lw);
                const int word = rown[ri] * HROW + w * 4 + tg;
                Nh[word] = hw; Nl[word] = lw;
            }
        }
        if (i >= 1) {            // h1(i-1)
            uint32_t* Nh = sH1hi + (1 - p) * HBUFW;
            const int tb = i - 1;
            #pragma unroll
            for (int ri = 0; ri < 2; ri++) {
                const bool upd = cv && (tb < lenr[ri]);
                #pragma unroll
                for (int j = 0; j < 2; j++) {
                    float zi = Dz[0][ri * 2 + j] + (j ? bi1 : bi0);
                    float zf = Dz[1][ri * 2 + j] + (j ? bf1 : bf0);
                    float zg = Dz[2][ri * 2 + j] + (j ? bg1 : bg0);
                    float zo = Dz[3][ri * 2 + j] + (j ? bo1 : bo0);
                    float cn = siga(zf) * c1[ri][j] + siga(zi) * tanha(zg);
                    float hn = siga(zo) * tanha(cn);
                    if (upd) { c1[ri][j] = cn; h1r[ri][j] = hn; }
                }
                const int word = rown[ri] * HROW + w * 4 + tg;
                Nh[word] = pack_h2(h1r[ri][0], h1r[ri][1]);
            }
        }
        __syncthreads();
        p ^= 1;
    }

    // ---- fc epilogue: out[perm] = h1_final . Wfc + b ----
    #pragma unroll
    for (int ri = 0; ri < 2; ri++) {
        if (cv) {
            sHF[rown[ri] * HSZ + u0]     = h1r[ri][0];
            sHF[rown[ri] * HSZ + u0 + 1] = h1r[ri][1];
        }
    }
    __syncthreads();
    if (tid < MROW) {
        float s = bfc[0];
        #pragma unroll 10
        for (int k = 0; k < HSZ; k++) s += sHF[tid * HSZ + k] * sWf[k];
        out[sPerm[tid]] = s;
    }
}

// ===========================================================================
// Launch
// ===========================================================================
extern "C" void kernel_launch(void* const* d_in, const int* in_sizes, int n_in,
                              void* d_out, int out_size)
{
    const float* x       = (const float*)d_in[0];
    const int*   lengths = (const int*)  d_in[1];
    const float* Wih0    = (const float*)d_in[2];
    const float* Whh0    = (const float*)d_in[3];
    const float* bih0    = (const float*)d_in[4];
    const float* bhh0    = (const float*)d_in[5];
    const float* Wih1    = (const float*)d_in[6];
    const float* Whh1    = (const float*)d_in[7];
    const float* bih1    = (const float*)d_in[8];
    const float* bhh1    = (const float*)d_in[9];
    const float* Wfc     = (const float*)d_in[10];
    const float* bfc     = (const float*)d_in[11];
    float* out = (float*)d_out;

    cudaFuncSetAttribute(k_fused, cudaFuncAttributeMaxDynamicSharedMemorySize, SMR);

    const int gridF = BSZ / MROW;   // 256 CTAs, longest first
    k_scan    <<<1, 512>>>(lengths);
    k_zx0     <<<128, 512>>>(x, lengths, Wih0, bih0, bhh0);
    k_sortperm<<<1, 512>>>(lengths);
    k_wprep3  <<<dim3((W2N + 255) / 256, 3), 256>>>(Whh0, Whh1, Wih1);
    k_fused   <<<gridF, RTH, SMR>>>(lengths, bih1, bhh1, Wfc, bfc, out);
}